// round 6
// baseline (speedup 1.0000x reference)
#include <cuda_runtime.h>
#include <math.h>

#define B_  64
#define S_  64
#define F_  2048
#define H_  512
#define G4_ 2048
#define P_  20
#define R_  4096   // B*S

#define LSTM_BLOCKS 128
#define PROTO_BLOCKS 20
#define TOTAL_BLOCKS (LSTM_BLOCKS + PROTO_BLOCKS)

// ---------------- scratch (static device globals; no allocs) ----------------
__device__ float g_fuse[R_ * H_];        // [B*S, H]   8 MB
__device__ float g_xg[S_ * B_ * G4_];    // [S][B][4H] 32 MB
__device__ float g_hT[2][H_ * B_];       // hidden state, TRANSPOSED [k][batch], double-buffered
__device__ float g_ddp[B_ * S_];         // per-(b,s) prototype partial
__device__ int   g_cat[B_];              // normalized category
__device__ unsigned g_bar_count = 0u;    // monotonic ticket counter (never reset)

__device__ __forceinline__ float sigmoidf_(float x) { return 1.0f / (1.0f + expf(-x)); }

// Ticket barrier over the 128 LSTM blocks: robust to any starting value that is
// ≡0 (mod 128); each full kernel run advances by 63*128, preserving that.
__device__ __forceinline__ void grid_bar_arrive_wait() {
    unsigned ticket = atomicAdd(&g_bar_count, 1u);
    unsigned target = (ticket & ~127u) + 128u;
    while (*((volatile unsigned*)&g_bar_count) < target) __nanosleep(32);
}

// ---------------- category dtype normalization (int64 vs int32) -------------
__global__ void cat_normalize(const int* __restrict__ w) {
    if (threadIdx.x == 0 && blockIdx.x == 0) {
        bool oddzero = true, evenok = true;
        for (int i = 0; i < 32; i++) {
            int lo = w[2 * i], hi = w[2 * i + 1];
            if (hi != 0) oddzero = false;
            if (lo < 0 || lo > 2) evenok = false;
        }
        if (oddzero && evenok) {  // little-endian int64 layout
            const long long* c = (const long long*)w;
            for (int b = 0; b < B_; b++) g_cat[b] = (int)c[b];
        } else {                  // int32 layout
            for (int b = 0; b < B_; b++) g_cat[b] = w[b];
        }
    }
}

// ---------------- fuse = relu(v @ W_enc + b_enc) + cat_emb[cat] --------------
// M=4096, N=512, K=2048. 128x128 tile, BK=8, 256 threads, 8x8 micro.
__global__ __launch_bounds__(256) void fuse_gemm(
    const float* __restrict__ A, const float* __restrict__ W,
    const float* __restrict__ bias, const float* __restrict__ cat_emb)
{
    __shared__ float As[8][132];
    __shared__ float Bs[8][128];
    const int tid  = threadIdx.x;
    const int brow = blockIdx.y * 128;
    const int bcol = blockIdx.x * 128;
    const int a_r = tid >> 1, a_c = (tid & 1) * 4;
    const int b_r = tid >> 5, b_c = (tid & 31) * 4;
    const int trow = (tid >> 4) * 8, tcol = (tid & 15) * 8;
    const int K = F_, N = H_;

    float acc[8][8];
    #pragma unroll
    for (int i = 0; i < 8; i++)
        #pragma unroll
        for (int j = 0; j < 8; j++) acc[i][j] = 0.0f;

    for (int k0 = 0; k0 < K; k0 += 8) {
        float4 av = *reinterpret_cast<const float4*>(&A[(size_t)(brow + a_r) * K + k0 + a_c]);
        As[a_c + 0][a_r] = av.x; As[a_c + 1][a_r] = av.y;
        As[a_c + 2][a_r] = av.z; As[a_c + 3][a_r] = av.w;
        float4 bv = *reinterpret_cast<const float4*>(&W[(size_t)(k0 + b_r) * N + bcol + b_c]);
        *reinterpret_cast<float4*>(&Bs[b_r][b_c]) = bv;
        __syncthreads();
        #pragma unroll
        for (int k = 0; k < 8; k++) {
            float ar[8], br[8];
            #pragma unroll
            for (int i = 0; i < 8; i++) ar[i] = As[k][trow + i];
            #pragma unroll
            for (int j = 0; j < 8; j++) br[j] = Bs[k][tcol + j];
            #pragma unroll
            for (int i = 0; i < 8; i++)
                #pragma unroll
                for (int j = 0; j < 8; j++) acc[i][j] = fmaf(ar[i], br[j], acc[i][j]);
        }
        __syncthreads();
    }
    #pragma unroll
    for (int i = 0; i < 8; i++) {
        int r = brow + trow + i;
        int b = r >> 6;
        const float* ce = &cat_emb[g_cat[b] * H_];
        #pragma unroll
        for (int j = 0; j < 8; j++) {
            int n = bcol + tcol + j;
            float v = acc[i][j] + bias[n];
            v = fmaxf(v, 0.0f) + ce[n];
            g_fuse[(size_t)r * H_ + n] = v;
        }
    }
}

// ---------------- x_gates[s][b][g] = fuse @ Wx + (bx+bh) ---------------------
// M=4096, N=2048, K=512.
__global__ __launch_bounds__(256) void xg_gemm(
    const float* __restrict__ W, const float* __restrict__ bx,
    const float* __restrict__ bh)
{
    __shared__ float As[8][132];
    __shared__ float Bs[8][128];
    const int tid  = threadIdx.x;
    const int brow = blockIdx.y * 128;
    const int bcol = blockIdx.x * 128;
    const int a_r = tid >> 1, a_c = (tid & 1) * 4;
    const int b_r = tid >> 5, b_c = (tid & 31) * 4;
    const int trow = (tid >> 4) * 8, tcol = (tid & 15) * 8;
    const int K = H_, N = G4_;

    float acc[8][8];
    #pragma unroll
    for (int i = 0; i < 8; i++)
        #pragma unroll
        for (int j = 0; j < 8; j++) acc[i][j] = 0.0f;

    for (int k0 = 0; k0 < K; k0 += 8) {
        float4 av = *reinterpret_cast<const float4*>(&g_fuse[(size_t)(brow + a_r) * K + k0 + a_c]);
        As[a_c + 0][a_r] = av.x; As[a_c + 1][a_r] = av.y;
        As[a_c + 2][a_r] = av.z; As[a_c + 3][a_r] = av.w;
        float4 bv = *reinterpret_cast<const float4*>(&W[(size_t)(k0 + b_r) * N + bcol + b_c]);
        *reinterpret_cast<float4*>(&Bs[b_r][b_c]) = bv;
        __syncthreads();
        #pragma unroll
        for (int k = 0; k < 8; k++) {
            float ar[8], br[8];
            #pragma unroll
            for (int i = 0; i < 8; i++) ar[i] = As[k][trow + i];
            #pragma unroll
            for (int j = 0; j < 8; j++) br[j] = Bs[k][tcol + j];
            #pragma unroll
            for (int i = 0; i < 8; i++)
                #pragma unroll
                for (int j = 0; j < 8; j++) acc[i][j] = fmaf(ar[i], br[j], acc[i][j]);
        }
        __syncthreads();
    }
    #pragma unroll
    for (int i = 0; i < 8; i++) {
        int r = brow + trow + i;
        int bb = r >> 6, ss = r & 63;
        size_t base = ((size_t)(ss * B_ + bb)) * G4_;
        #pragma unroll
        for (int j = 0; j < 8; j++) {
            int n = bcol + tcol + j;
            g_xg[base + n] = acc[i][j] + bx[n] + bh[n];
        }
    }
}

// ---------------- persistent LSTM + co-resident proto work -------------------
// 148 blocks x 512 threads, 1 block/SM (196KB smem), single wave.
// Blocks 0..127:  LSTM. Block b owns h cols [4b,4b+4) => 16 gate cols.
//   512 threads = 8 K-octants (64 k each) x 64 output threads (4 rows x 4 cols).
//   Each octant loads ONLY its 16KB h slice, syncs via 64-thread named barrier.
// Blocks 128..147: prototype-distance work (fills g_ddp) on otherwise-idle SMs.
__global__ __launch_bounds__(512) void lstm_persist(
    const float* __restrict__ Wh,
    const float* __restrict__ v, const float* __restrict__ proto,
    const float* __restrict__ W_dd)
{
    extern __shared__ float sm[];
    const int tid = threadIdx.x;

    // ================= proto path (blocks 128..147) =================
    if (blockIdx.x >= LSTM_BLOCKS) {
        float* wsum = sm;                 // [16][P_]
        float* psum = sm + 16 * P_;       // [P_]
        const int pb = blockIdx.x - LSTM_BLOCKS;
        const int wid = tid >> 5, lane = tid & 31;

        for (int r = pb; r < R_; r += PROTO_BLOCKS) {
            const int s = r & 63;
            const float* vrow = &v[(size_t)r * F_];
            float acc[P_];
            #pragma unroll
            for (int p = 0; p < P_; p++) acc[p] = 0.0f;
            for (int f = tid; f < F_; f += 512) {
                float vv = vrow[f];
                #pragma unroll
                for (int p = 0; p < P_; p++) {
                    float d = vv - proto[p * F_ + f];
                    acc[p] = fmaf(d, d, acc[p]);
                }
            }
            #pragma unroll
            for (int p = 0; p < P_; p++) {
                float x = acc[p];
                #pragma unroll
                for (int o = 16; o > 0; o >>= 1) x += __shfl_down_sync(0xffffffffu, x, o);
                acc[p] = x;
            }
            if (lane == 0)
                for (int p = 0; p < P_; p++) wsum[wid * P_ + p] = acc[p];
            __syncthreads();
            if (tid < P_) {
                float d = 0.0f;
                #pragma unroll
                for (int w = 0; w < 16; w++) d += wsum[w * P_ + tid];
                float df = logf((d + 1.0f) / (d + 1e-8f));
                psum[tid] = df * W_dd[s * P_ + tid];
            }
            __syncthreads();
            if (tid == 0) {
                float t = 0.0f;
                for (int p = 0; p < P_; p++) t += psum[p];
                g_ddp[r] = t;
            }
            __syncthreads();
        }
        return;
    }

    // ================= LSTM path (blocks 0..127) =================
    float* whs = sm;                        // [512][16]     32 KB
    float* as_ = sm + 512 * 16;             // [512][64]     128 KB
    float* gs_ = as_ + 512 * 64;            // [8][64*17]    partial gates per octant
    float* cs_ = gs_ + 8 * 64 * 17;         // [64][4]       cell state

    const int jbase = blockIdx.x * 4;

    const int kq = tid >> 6;                // K-octant 0..7 (64 k each)
    const int t  = tid & 63;
    const int tr4 = (t & 15) * 4;           // rows tr4..tr4+3
    const int c4  = (t >> 4) * 4;           // gate-cols c4..c4+3

    // cell-update mapping (tid < 256): thread -> (m, jl), jl fastest
    const int cm  = (tid & 255) >> 2;
    const int cjl = tid & 3;

    // preload Wh tile: whs[k][c], c = g*4+jl -> global col g*512 + jbase + jl
    for (int idx = tid; idx < 512 * 16; idx += 512) {
        int k = idx >> 4, c = idx & 15;
        whs[idx] = Wh[(size_t)k * G4_ + (c >> 2) * H_ + jbase + (c & 3)];
    }
    if (tid < 256) cs_[tid] = 0.0f;
    __syncthreads();

    for (int s = 0; s < S_; s++) {
        const float* __restrict__ hT_in = g_hT[s & 1];
        float* __restrict__ hT_out      = g_hT[(s + 1) & 1];
        const float* __restrict__ xg_s  = &g_xg[(size_t)s * B_ * G4_];

        float acc[4][4];
        #pragma unroll
        for (int i = 0; i < 4; i++)
            #pragma unroll
            for (int j = 0; j < 4; j++) acc[i][j] = 0.0f;

        if (s > 0) {
            // ---- load this octant's h slice (16 KB), coalesced ----
            const float4* src = reinterpret_cast<const float4*>(hT_in) + kq * 1024;
            float4* dst = reinterpret_cast<float4*>(as_ + kq * 4096);
            #pragma unroll
            for (int i = 0; i < 16; i++) {
                int f = t + i * 64;
                dst[f] = __ldcg(&src[f]);
            }
            // octant-local barrier (2 warps, 64 threads)
            asm volatile("bar.sync %0, 64;" :: "r"(1 + kq) : "memory");

            // ---- GEMM: 4 rows x 4 cols over this octant's 64 k ----
            const float* ap = &as_[(kq * 64) * 64 + tr4];
            const float* bp = &whs[(kq * 64) * 16 + c4];
            #pragma unroll 8
            for (int k = 0; k < 64; k++) {
                float4 a = *reinterpret_cast<const float4*>(ap); ap += 64;
                float4 b = *reinterpret_cast<const float4*>(bp); bp += 16;
                acc[0][0] = fmaf(a.x, b.x, acc[0][0]);
                acc[1][0] = fmaf(a.y, b.x, acc[1][0]);
                acc[2][0] = fmaf(a.z, b.x, acc[2][0]);
                acc[3][0] = fmaf(a.w, b.x, acc[3][0]);
                acc[0][1] = fmaf(a.x, b.y, acc[0][1]);
                acc[1][1] = fmaf(a.y, b.y, acc[1][1]);
                acc[2][1] = fmaf(a.z, b.y, acc[2][1]);
                acc[3][1] = fmaf(a.w, b.y, acc[3][1]);
                acc[0][2] = fmaf(a.x, b.z, acc[0][2]);
                acc[1][2] = fmaf(a.y, b.z, acc[1][2]);
                acc[2][2] = fmaf(a.z, b.z, acc[2][2]);
                acc[3][2] = fmaf(a.w, b.z, acc[3][2]);
                acc[0][3] = fmaf(a.x, b.w, acc[0][3]);
                acc[1][3] = fmaf(a.y, b.w, acc[1][3]);
                acc[2][3] = fmaf(a.z, b.w, acc[2][3]);
                acc[3][3] = fmaf(a.w, b.w, acc[3][3]);
            }
        }

        // ---- write partial gates (stride 17; zeros at s==0 keep it uniform) --
        {
            float* gq = gs_ + kq * (64 * 17);
            #pragma unroll
            for (int i = 0; i < 4; i++) {
                #pragma unroll
                for (int j = 0; j < 4; j++)
                    gq[(tr4 + i) * 17 + c4 + j] = acc[i][j];
            }
        }
        __syncthreads();

        // ---- fused cell update (tid < 256: one thread per (m, jl)) ----
        if (tid < 256) {
            const int m = cm, jl = cjl;
            float gv[4];
            #pragma unroll
            for (int g = 0; g < 4; g++) {
                float x = xg_s[(size_t)m * G4_ + g * H_ + jbase + jl];
                int o = m * 17 + g * 4 + jl;
                #pragma unroll
                for (int q = 0; q < 8; q++) x += gs_[q * (64 * 17) + o];
                gv[g] = x;
            }
            float co = cs_[m * 4 + jl];
            float cn = sigmoidf_(gv[1]) * co + sigmoidf_(gv[0]) * tanhf(gv[3]);
            float hn = sigmoidf_(gv[2]) * cn;   // NOTE: no tanh on cell in this model
            cs_[m * 4 + jl] = cn;
            __stcg(&hT_out[(jbase + jl) * B_ + m], hn);
        }

        // ---- grid barrier between steps (128 LSTM blocks only) ----
        if (s + 1 < S_) {
            __threadfence();
            __syncthreads();
            if (tid == 0) {
                grid_bar_arrive_wait();
                __threadfence();
            }
            __syncthreads();
        }
    }
}

// ---------------- final combine per batch ------------------------------------
__global__ __launch_bounds__(256) void final_kernel(
    const float* __restrict__ v, const float* __restrict__ W_dec,
    const float* __restrict__ b_dec, const float* __restrict__ W_gate,
    const float* __restrict__ b_gate, const float* __restrict__ b_dd,
    float* __restrict__ out)
{
    const int b = blockIdx.x;
    const int tid = threadIdx.x;

    float hd = 0.0f;
    for (int k = tid; k < H_; k += 256)
        hd += g_hT[0][k * B_ + b] * W_dec[k];   // after 64 steps h lives in buf 0

    float gs = 0.0f;
    const float* vb = &v[(size_t)b * S_ * F_];
    for (int idx = tid; idx < S_ * F_; idx += 256)
        gs += vb[idx] * W_gate[idx & (F_ - 1)];

    float ds = 0.0f;
    for (int s = tid; s < S_; s += 256)
        ds += g_ddp[b * S_ + s];

    __shared__ float red[3][256];
    red[0][tid] = hd; red[1][tid] = gs; red[2][tid] = ds;
    __syncthreads();
    for (int o = 128; o > 0; o >>= 1) {
        if (tid < o) {
            red[0][tid] += red[0][tid + o];
            red[1][tid] += red[1][tid + o];
            red[2][tid] += red[2][tid + o];
        }
        __syncthreads();
    }
    if (tid == 0) {
        float gt = sigmoidf_(red[1][0] * (1.0f / S_) + b_gate[0]);
        float op = sigmoidf_(red[0][0] + b_dec[0]);
        float dp = sigmoidf_(red[2][0] + b_dd[0]);
        out[b] = op * gt + dp * (1.0f - gt);
    }
}

// ---------------- launch ------------------------------------------------------
extern "C" void kernel_launch(void* const* d_in, const int* in_sizes, int n_in,
                              void* d_out, int out_size)
{
    const float* v       = (const float*)d_in[0];
    const int*   cat     = (const int*)d_in[1];
    const float* W_enc   = (const float*)d_in[2];
    const float* b_enc   = (const float*)d_in[3];
    const float* Wx      = (const float*)d_in[4];
    const float* bx      = (const float*)d_in[5];
    const float* Wh      = (const float*)d_in[6];
    const float* bh      = (const float*)d_in[7];
    const float* cat_emb = (const float*)d_in[8];
    const float* W_dec   = (const float*)d_in[9];
    const float* b_dec   = (const float*)d_in[10];
    const float* proto   = (const float*)d_in[11];
    const float* W_dd    = (const float*)d_in[12];
    const float* b_dd    = (const float*)d_in[13];
    const float* W_gate  = (const float*)d_in[14];
    const float* b_gate  = (const float*)d_in[15];
    float* out = (float*)d_out;

    const int lstm_smem = (512 * 16 + 512 * 64 + 8 * 64 * 17 + 64 * 4) * 4;
    cudaFuncSetAttribute(lstm_persist, cudaFuncAttributeMaxDynamicSharedMemorySize,
                         lstm_smem);

    cat_normalize<<<1, 32>>>(cat);
    fuse_gemm<<<dim3(H_ / 128, R_ / 128), 256>>>(v, W_enc, b_enc, cat_emb);
    xg_gemm<<<dim3(G4_ / 128, R_ / 128), 256>>>(Wx, bx, bh);
    lstm_persist<<<TOTAL_BLOCKS, 512, lstm_smem>>>(Wh, v, proto, W_dd);
    final_kernel<<<B_, 256>>>(v, W_dec, b_dec, W_gate, b_gate, b_dd, out);
}

// round 7
// speedup vs baseline: 1.3879x; 1.3879x over previous
#include <cuda_runtime.h>
#include <math.h>

#define B_  64
#define S_  64
#define F_  2048
#define H_  512
#define G4_ 2048
#define P_  20
#define R_  4096   // B*S

// ---------------- scratch (static device globals; no allocs) ----------------
__device__ float g_fuse[R_ * H_];        // [B*S, H]   8 MB
__device__ float g_xg[S_ * B_ * G4_];    // [S][B][4H] 32 MB
__device__ float g_hT[2][H_ * B_];       // hidden state, TRANSPOSED [k][batch], double-buffered
__device__ float g_ddp[B_ * S_];         // per-(b,s) prototype partial
__device__ int   g_cat[B_];              // normalized category
__device__ unsigned g_bar_count = 0u;    // monotonic ticket counter (never reset)

__device__ __forceinline__ float sigmoidf_(float x) { return 1.0f / (1.0f + expf(-x)); }

// Ticket barrier: robust to any starting value ≡0 (mod 128); each run advances
// by 63*128, preserving that invariant across replays.
__device__ __forceinline__ void grid_bar_arrive_wait() {
    unsigned ticket = atomicAdd(&g_bar_count, 1u);
    unsigned target = (ticket & ~127u) + 128u;
    while (*((volatile unsigned*)&g_bar_count) < target) __nanosleep(32);
}

// ---------------- category dtype normalization (int64 vs int32) -------------
__global__ void cat_normalize(const int* __restrict__ w) {
    if (threadIdx.x == 0 && blockIdx.x == 0) {
        bool oddzero = true, evenok = true;
        for (int i = 0; i < 32; i++) {
            int lo = w[2 * i], hi = w[2 * i + 1];
            if (hi != 0) oddzero = false;
            if (lo < 0 || lo > 2) evenok = false;
        }
        if (oddzero && evenok) {  // little-endian int64 layout
            const long long* c = (const long long*)w;
            for (int b = 0; b < B_; b++) g_cat[b] = (int)c[b];
        } else {                  // int32 layout
            for (int b = 0; b < B_; b++) g_cat[b] = w[b];
        }
    }
}

// ---------------- fuse = relu(v @ W_enc + b_enc) + cat_emb[cat] --------------
// M=4096, N=512, K=2048. 128x128 tile, BK=8, 256 threads, 8x8 micro.
__global__ __launch_bounds__(256) void fuse_gemm(
    const float* __restrict__ A, const float* __restrict__ W,
    const float* __restrict__ bias, const float* __restrict__ cat_emb)
{
    __shared__ float As[8][132];
    __shared__ float Bs[8][128];
    const int tid  = threadIdx.x;
    const int brow = blockIdx.y * 128;
    const int bcol = blockIdx.x * 128;
    const int a_r = tid >> 1, a_c = (tid & 1) * 4;
    const int b_r = tid >> 5, b_c = (tid & 31) * 4;
    const int trow = (tid >> 4) * 8, tcol = (tid & 15) * 8;
    const int K = F_, N = H_;

    float acc[8][8];
    #pragma unroll
    for (int i = 0; i < 8; i++)
        #pragma unroll
        for (int j = 0; j < 8; j++) acc[i][j] = 0.0f;

    for (int k0 = 0; k0 < K; k0 += 8) {
        float4 av = *reinterpret_cast<const float4*>(&A[(size_t)(brow + a_r) * K + k0 + a_c]);
        As[a_c + 0][a_r] = av.x; As[a_c + 1][a_r] = av.y;
        As[a_c + 2][a_r] = av.z; As[a_c + 3][a_r] = av.w;
        float4 bv = *reinterpret_cast<const float4*>(&W[(size_t)(k0 + b_r) * N + bcol + b_c]);
        *reinterpret_cast<float4*>(&Bs[b_r][b_c]) = bv;
        __syncthreads();
        #pragma unroll
        for (int k = 0; k < 8; k++) {
            float ar[8], br[8];
            #pragma unroll
            for (int i = 0; i < 8; i++) ar[i] = As[k][trow + i];
            #pragma unroll
            for (int j = 0; j < 8; j++) br[j] = Bs[k][tcol + j];
            #pragma unroll
            for (int i = 0; i < 8; i++)
                #pragma unroll
                for (int j = 0; j < 8; j++) acc[i][j] = fmaf(ar[i], br[j], acc[i][j]);
        }
        __syncthreads();
    }
    #pragma unroll
    for (int i = 0; i < 8; i++) {
        int r = brow + trow + i;
        int b = r >> 6;
        const float* ce = &cat_emb[g_cat[b] * H_];
        #pragma unroll
        for (int j = 0; j < 8; j++) {
            int n = bcol + tcol + j;
            float v = acc[i][j] + bias[n];
            v = fmaxf(v, 0.0f) + ce[n];
            g_fuse[(size_t)r * H_ + n] = v;
        }
    }
}

// ---------------- x_gates[s][b][g] = fuse @ Wx + (bx+bh) ---------------------
// M=4096, N=2048, K=512.
__global__ __launch_bounds__(256) void xg_gemm(
    const float* __restrict__ W, const float* __restrict__ bx,
    const float* __restrict__ bh)
{
    __shared__ float As[8][132];
    __shared__ float Bs[8][128];
    const int tid  = threadIdx.x;
    const int brow = blockIdx.y * 128;
    const int bcol = blockIdx.x * 128;
    const int a_r = tid >> 1, a_c = (tid & 1) * 4;
    const int b_r = tid >> 5, b_c = (tid & 31) * 4;
    const int trow = (tid >> 4) * 8, tcol = (tid & 15) * 8;
    const int K = H_, N = G4_;

    float acc[8][8];
    #pragma unroll
    for (int i = 0; i < 8; i++)
        #pragma unroll
        for (int j = 0; j < 8; j++) acc[i][j] = 0.0f;

    for (int k0 = 0; k0 < K; k0 += 8) {
        float4 av = *reinterpret_cast<const float4*>(&g_fuse[(size_t)(brow + a_r) * K + k0 + a_c]);
        As[a_c + 0][a_r] = av.x; As[a_c + 1][a_r] = av.y;
        As[a_c + 2][a_r] = av.z; As[a_c + 3][a_r] = av.w;
        float4 bv = *reinterpret_cast<const float4*>(&W[(size_t)(k0 + b_r) * N + bcol + b_c]);
        *reinterpret_cast<float4*>(&Bs[b_r][b_c]) = bv;
        __syncthreads();
        #pragma unroll
        for (int k = 0; k < 8; k++) {
            float ar[8], br[8];
            #pragma unroll
            for (int i = 0; i < 8; i++) ar[i] = As[k][trow + i];
            #pragma unroll
            for (int j = 0; j < 8; j++) br[j] = Bs[k][tcol + j];
            #pragma unroll
            for (int i = 0; i < 8; i++)
                #pragma unroll
                for (int j = 0; j < 8; j++) acc[i][j] = fmaf(ar[i], br[j], acc[i][j]);
        }
        __syncthreads();
    }
    #pragma unroll
    for (int i = 0; i < 8; i++) {
        int r = brow + trow + i;
        int bb = r >> 6, ss = r & 63;
        size_t base = ((size_t)(ss * B_ + bb)) * G4_;
        #pragma unroll
        for (int j = 0; j < 8; j++) {
            int n = bcol + tcol + j;
            g_xg[base + n] = acc[i][j] + bx[n] + bh[n];
        }
    }
}

// ---------------- persistent LSTM: all 64 steps in one kernel ----------------
// 128 blocks x 256 threads. Block owns h cols [4b,4b+4) => 16 gate cols.
// 8 warps = 8 K-groups of 64 k. Each WARP loads its own 16KB h slice and
// consumes it itself -> no intra-step block barriers, load pipelines with
// compute per warp. Thread tile 4 rows x 8 cols: 3 LDS.128 per 32 FFMA
// (crossbar 6144 cyc < FFMA floor 8192 cyc => FFMA-bound).
__global__ __launch_bounds__(256) void lstm_persist(const float* __restrict__ Wh)
{
    extern __shared__ float sm[];
    float* whs = sm;                        // [512][16]   32 KB
    float* as_ = sm + 512 * 16;             // [512][64]   128 KB
    float* gs_ = as_ + 512 * 64;            // [8][64*17]  partial gates per warp
    float* cs_ = gs_ + 8 * 64 * 17;         // [64][4]     cell state

    const int tid   = threadIdx.x;
    const int jbase = blockIdx.x * 4;

    const int w = tid >> 5;                 // warp = K-group (64 k each)
    const int l = tid & 31;
    const int r4 = (l & 15) * 4;            // rows r4..r4+3
    const int c8 = (l >> 4) * 8;            // gate-cols c8..c8+7

    // cell-update mapping: thread -> (m, jl), jl fastest (coalesced xg)
    const int cm  = tid >> 2;
    const int cjl = tid & 3;

    // preload Wh tile: whs[k][c], c = g*4+jl -> global col g*512 + jbase + jl
    for (int idx = tid; idx < 512 * 16; idx += 256) {
        int k = idx >> 4, c = idx & 15;
        whs[idx] = Wh[(size_t)k * G4_ + (c >> 2) * H_ + jbase + (c & 3)];
    }
    cs_[tid] = 0.0f;   // 256 entries = all of [64][4]
    __syncthreads();

    for (int s = 0; s < S_; s++) {
        const float* __restrict__ hT_in = g_hT[s & 1];
        float* __restrict__ hT_out      = g_hT[(s + 1) & 1];
        const float* __restrict__ xg_s  = &g_xg[(size_t)s * B_ * G4_];

        float acc[4][8];
        #pragma unroll
        for (int i = 0; i < 4; i++)
            #pragma unroll
            for (int j = 0; j < 8; j++) acc[i][j] = 0.0f;

        if (s > 0) {
            // ---- warp loads its own 16KB h slice (k in [w*64, w*64+64)) ----
            const float4* src = reinterpret_cast<const float4*>(hT_in) + w * 1024;
            float4* dst = reinterpret_cast<float4*>(as_ + w * 64 * 64);
            #pragma unroll
            for (int i = 0; i < 32; i++) {
                int f = l + i * 32;
                dst[f] = __ldcg(&src[f]);
            }
            __syncwarp();

            // ---- GEMM: 4 rows x 8 cols over this warp's 64 k ----
            const float* ap = &as_[(w * 64) * 64 + r4];
            const float* bp = &whs[(w * 64) * 16 + c8];
            #pragma unroll 8
            for (int k = 0; k < 64; k++) {
                float4 a  = *reinterpret_cast<const float4*>(ap); ap += 64;
                float4 b0 = *reinterpret_cast<const float4*>(bp);
                float4 b1 = *reinterpret_cast<const float4*>(bp + 4); bp += 16;
                acc[0][0] = fmaf(a.x, b0.x, acc[0][0]);
                acc[1][0] = fmaf(a.y, b0.x, acc[1][0]);
                acc[2][0] = fmaf(a.z, b0.x, acc[2][0]);
                acc[3][0] = fmaf(a.w, b0.x, acc[3][0]);
                acc[0][1] = fmaf(a.x, b0.y, acc[0][1]);
                acc[1][1] = fmaf(a.y, b0.y, acc[1][1]);
                acc[2][1] = fmaf(a.z, b0.y, acc[2][1]);
                acc[3][1] = fmaf(a.w, b0.y, acc[3][1]);
                acc[0][2] = fmaf(a.x, b0.z, acc[0][2]);
                acc[1][2] = fmaf(a.y, b0.z, acc[1][2]);
                acc[2][2] = fmaf(a.z, b0.z, acc[2][2]);
                acc[3][2] = fmaf(a.w, b0.z, acc[3][2]);
                acc[0][3] = fmaf(a.x, b0.w, acc[0][3]);
                acc[1][3] = fmaf(a.y, b0.w, acc[1][3]);
                acc[2][3] = fmaf(a.z, b0.w, acc[2][3]);
                acc[3][3] = fmaf(a.w, b0.w, acc[3][3]);
                acc[0][4] = fmaf(a.x, b1.x, acc[0][4]);
                acc[1][4] = fmaf(a.y, b1.x, acc[1][4]);
                acc[2][4] = fmaf(a.z, b1.x, acc[2][4]);
                acc[3][4] = fmaf(a.w, b1.x, acc[3][4]);
                acc[0][5] = fmaf(a.x, b1.y, acc[0][5]);
                acc[1][5] = fmaf(a.y, b1.y, acc[1][5]);
                acc[2][5] = fmaf(a.z, b1.y, acc[2][5]);
                acc[3][5] = fmaf(a.w, b1.y, acc[3][5]);
                acc[0][6] = fmaf(a.x, b1.z, acc[0][6]);
                acc[1][6] = fmaf(a.y, b1.z, acc[1][6]);
                acc[2][6] = fmaf(a.z, b1.z, acc[2][6]);
                acc[3][6] = fmaf(a.w, b1.z, acc[3][6]);
                acc[0][7] = fmaf(a.x, b1.w, acc[0][7]);
                acc[1][7] = fmaf(a.y, b1.w, acc[1][7]);
                acc[2][7] = fmaf(a.z, b1.w, acc[2][7]);
                acc[3][7] = fmaf(a.w, b1.w, acc[3][7]);
            }
        }

        // ---- write partial gates (stride 17; zeros at s==0 keep it uniform) --
        {
            float* gq = gs_ + w * (64 * 17);
            #pragma unroll
            for (int i = 0; i < 4; i++) {
                #pragma unroll
                for (int j = 0; j < 8; j++)
                    gq[(r4 + i) * 17 + c8 + j] = acc[i][j];
            }
        }
        __syncthreads();

        // ---- fused cell update (one thread per (m, jl)) ----
        {
            const int m = cm, jl = cjl;
            float gv[4];
            #pragma unroll
            for (int g = 0; g < 4; g++) {
                float x = xg_s[(size_t)m * G4_ + g * H_ + jbase + jl];
                int o = m * 17 + g * 4 + jl;
                #pragma unroll
                for (int q = 0; q < 8; q++) x += gs_[q * (64 * 17) + o];
                gv[g] = x;
            }
            float co = cs_[m * 4 + jl];
            float cn = sigmoidf_(gv[1]) * co + sigmoidf_(gv[0]) * tanhf(gv[3]);
            float hn = sigmoidf_(gv[2]) * cn;   // NOTE: no tanh on cell in this model
            cs_[m * 4 + jl] = cn;
            __stcg(&hT_out[(jbase + jl) * B_ + m], hn);
        }

        // ---- grid barrier between steps ----
        if (s + 1 < S_) {
            __threadfence();
            __syncthreads();
            if (tid == 0) {
                grid_bar_arrive_wait();
                __threadfence();
            }
            __syncthreads();
        }
    }
}

// ---------------- prototype distances -> per-(b,s) W_dd partial --------------
__global__ __launch_bounds__(128) void proto_kernel(
    const float* __restrict__ v, const float* __restrict__ proto,
    const float* __restrict__ W_dd)
{
    const int r = blockIdx.x;          // b*S + s
    const int s = r & 63;
    const int tid = threadIdx.x;
    const float* vrow = &v[(size_t)r * F_];

    float acc[P_];
    #pragma unroll
    for (int p = 0; p < P_; p++) acc[p] = 0.0f;

    for (int f = tid; f < F_; f += 128) {
        float vv = vrow[f];
        #pragma unroll
        for (int p = 0; p < P_; p++) {
            float d = vv - proto[p * F_ + f];
            acc[p] = fmaf(d, d, acc[p]);
        }
    }
    #pragma unroll
    for (int p = 0; p < P_; p++) {
        float x = acc[p];
        #pragma unroll
        for (int o = 16; o > 0; o >>= 1) x += __shfl_down_sync(0xffffffffu, x, o);
        acc[p] = x;
    }
    __shared__ float wsum[4][P_];
    __shared__ float psum[P_];
    int wid = tid >> 5, lane = tid & 31;
    if (lane == 0)
        for (int p = 0; p < P_; p++) wsum[wid][p] = acc[p];
    __syncthreads();
    if (tid < P_) {
        float d = wsum[0][tid] + wsum[1][tid] + wsum[2][tid] + wsum[3][tid];
        float df = logf((d + 1.0f) / (d + 1e-8f));
        psum[tid] = df * W_dd[s * P_ + tid];
    }
    __syncthreads();
    if (tid == 0) {
        float t = 0.0f;
        for (int p = 0; p < P_; p++) t += psum[p];
        g_ddp[r] = t;
    }
}

// ---------------- final combine per batch ------------------------------------
__global__ __launch_bounds__(256) void final_kernel(
    const float* __restrict__ v, const float* __restrict__ W_dec,
    const float* __restrict__ b_dec, const float* __restrict__ W_gate,
    const float* __restrict__ b_gate, const float* __restrict__ b_dd,
    float* __restrict__ out)
{
    const int b = blockIdx.x;
    const int tid = threadIdx.x;

    float hd = 0.0f;
    for (int k = tid; k < H_; k += 256)
        hd += g_hT[0][k * B_ + b] * W_dec[k];   // after 64 steps h lives in buf 0

    float gs = 0.0f;
    const float* vb = &v[(size_t)b * S_ * F_];
    for (int idx = tid; idx < S_ * F_; idx += 256)
        gs += vb[idx] * W_gate[idx & (F_ - 1)];

    float ds = 0.0f;
    for (int s = tid; s < S_; s += 256)
        ds += g_ddp[b * S_ + s];

    __shared__ float red[3][256];
    red[0][tid] = hd; red[1][tid] = gs; red[2][tid] = ds;
    __syncthreads();
    for (int o = 128; o > 0; o >>= 1) {
        if (tid < o) {
            red[0][tid] += red[0][tid + o];
            red[1][tid] += red[1][tid + o];
            red[2][tid] += red[2][tid + o];
        }
        __syncthreads();
    }
    if (tid == 0) {
        float gt = sigmoidf_(red[1][0] * (1.0f / S_) + b_gate[0]);
        float op = sigmoidf_(red[0][0] + b_dec[0]);
        float dp = sigmoidf_(red[2][0] + b_dd[0]);
        out[b] = op * gt + dp * (1.0f - gt);
    }
}

// ---------------- launch ------------------------------------------------------
extern "C" void kernel_launch(void* const* d_in, const int* in_sizes, int n_in,
                              void* d_out, int out_size)
{
    const float* v       = (const float*)d_in[0];
    const int*   cat     = (const int*)d_in[1];
    const float* W_enc   = (const float*)d_in[2];
    const float* b_enc   = (const float*)d_in[3];
    const float* Wx      = (const float*)d_in[4];
    const float* bx      = (const float*)d_in[5];
    const float* Wh      = (const float*)d_in[6];
    const float* bh      = (const float*)d_in[7];
    const float* cat_emb = (const float*)d_in[8];
    const float* W_dec   = (const float*)d_in[9];
    const float* b_dec   = (const float*)d_in[10];
    const float* proto   = (const float*)d_in[11];
    const float* W_dd    = (const float*)d_in[12];
    const float* b_dd    = (const float*)d_in[13];
    const float* W_gate  = (const float*)d_in[14];
    const float* b_gate  = (const float*)d_in[15];
    float* out = (float*)d_out;

    const int lstm_smem = (512 * 16 + 512 * 64 + 8 * 64 * 17 + 64 * 4) * 4;
    cudaFuncSetAttribute(lstm_persist, cudaFuncAttributeMaxDynamicSharedMemorySize,
                         lstm_smem);

    cat_normalize<<<1, 32>>>(cat);
    fuse_gemm<<<dim3(H_ / 128, R_ / 128), 256>>>(v, W_enc, b_enc, cat_emb);
    xg_gemm<<<dim3(G4_ / 128, R_ / 128), 256>>>(Wx, bx, bh);
    lstm_persist<<<128, 256, lstm_smem>>>(Wh);
    proto_kernel<<<R_, 128>>>(v, proto, W_dd);
    final_kernel<<<B_, 256>>>(v, W_dec, b_dec, W_gate, b_gate, b_dd, out);
}

// round 8
// speedup vs baseline: 1.6712x; 1.2041x over previous
#include <cuda_runtime.h>
#include <math.h>
#include <stdint.h>

#define B_  64
#define S_  64
#define F_  2048
#define H_  512
#define G4_ 2048
#define P_  20
#define R_  4096   // B*S

// ---------------- scratch (static device globals; no allocs) ----------------
__device__ float g_fuse[R_ * H_];        // [B*S, H]   8 MB
__device__ float g_xg[S_ * B_ * G4_];    // [S][B][4H] 32 MB
__device__ float g_hT[2][H_ * B_];       // hidden state, TRANSPOSED [k][batch]
__device__ float g_ddp[B_ * S_];         // per-(b,s) prototype partial
__device__ int   g_cat[B_];              // normalized category
__device__ unsigned g_bar_count = 0u;    // monotonic ticket counter (never reset)

__device__ __forceinline__ float sigmoidf_(float x) { return 1.0f / (1.0f + expf(-x)); }

__device__ __forceinline__ void grid_bar_arrive_wait() {
    unsigned ticket = atomicAdd(&g_bar_count, 1u);
    unsigned target = (ticket & ~127u) + 128u;
    while (*((volatile unsigned*)&g_bar_count) < target) __nanosleep(32);
}

// ---------------- category dtype normalization (int64 vs int32) -------------
__global__ void cat_normalize(const int* __restrict__ w) {
    if (threadIdx.x == 0 && blockIdx.x == 0) {
        bool oddzero = true, evenok = true;
        for (int i = 0; i < 32; i++) {
            int lo = w[2 * i], hi = w[2 * i + 1];
            if (hi != 0) oddzero = false;
            if (lo < 0 || lo > 2) evenok = false;
        }
        if (oddzero && evenok) {
            const long long* c = (const long long*)w;
            for (int b = 0; b < B_; b++) g_cat[b] = (int)c[b];
        } else {
            for (int b = 0; b < B_; b++) g_cat[b] = w[b];
        }
    }
}

// =================== tf32 tensor-core GEMM (both big GEMMs) ==================
// Block tile 128(M) x 64(N) x 32(K), 256 threads = 8 warps in 4x2 grid,
// warp tile 32x32 (2 m-tiles x 4 n-tiles of m16n8k8). Fragment-packed smem:
// A: [k8][mtile][lane][4] (LDS.128), B: [k8][ntile][lane][2] (LDS.64).
#define TBM 128
#define TBN 64
#define TBK 32
#define AS_FLOATS 4096          // 4 k8 * 8 mtile * 32 * 4
#define BUF_FLOATS 6144         // + 4 k8 * 8 ntile * 32 * 2

__device__ __forceinline__ unsigned f2tf32(float x) {
    unsigned u;
    asm("cvt.rna.tf32.f32 %0, %1;" : "=r"(u) : "f"(x));
    return u;
}

template<int KDIM, int NDIM>
__device__ __forceinline__ void tf32_mainloop(
    const float* __restrict__ A, const float* __restrict__ W,
    float* sm, int brow, int bcol, float (&acc)[8][4])
{
    const int tid  = threadIdx.x;
    const int lane = tid & 31;
    const int wid  = tid >> 5;
    const int wm   = wid >> 1;   // 0..3
    const int wn   = wid & 1;    // 0..1

    #pragma unroll
    for (int i = 0; i < 8; i++)
        #pragma unroll
        for (int j = 0; j < 4; j++) acc[i][j] = 0.0f;

    float4 a_ld[4], b_ld[2];

    auto load_g = [&](int kt) {
        #pragma unroll
        for (int j = 0; j < 4; j++) {
            int r = (tid >> 3) + j * 32;
            a_ld[j] = *reinterpret_cast<const float4*>(
                &A[(size_t)(brow + r) * KDIM + kt * TBK + (tid & 7) * 4]);
        }
        #pragma unroll
        for (int j = 0; j < 2; j++) {
            int f = tid + j * 256;
            int kr = f >> 4, c4 = (f & 15) * 4;
            b_ld[j] = *reinterpret_cast<const float4*>(
                &W[(size_t)(kt * TBK + kr) * NDIM + bcol + c4]);
        }
    };

    auto sts = [&](float* buf) {
        // A fragments
        #pragma unroll
        for (int j = 0; j < 4; j++) {
            int r = (tid >> 3) + j * 32;
            int c = (tid & 7) * 4;
            int mtile = r >> 4, rr = r & 15;
            int k8 = c >> 3;
            int sbase = (rr >> 3) + 2 * ((c >> 2) & 1);
            int lbase = (rr & 7) * 4;
            float* dst = buf + ((k8 * 8 + mtile) * 32) * 4 + sbase;
            const float* src = (const float*)&a_ld[j];
            #pragma unroll
            for (int i = 0; i < 4; i++)
                dst[(lbase + i) * 4] = __uint_as_float(f2tf32(src[i]));
        }
        // B fragments
        #pragma unroll
        for (int j = 0; j < 2; j++) {
            int f = tid + j * 256;
            int kr = f >> 4, c4 = (f & 15) * 4;
            int k8 = kr >> 3, kk = kr & 7;
            int slot = kk >> 2, lrow = kk & 3;
            const float* src = (const float*)&b_ld[j];
            #pragma unroll
            for (int i = 0; i < 4; i++) {
                int c = c4 + i;
                int ntile = c >> 3, cc = c & 7;
                buf[AS_FLOATS + ((k8 * 8 + ntile) * 32 + cc * 4 + lrow) * 2 + slot] =
                    __uint_as_float(f2tf32(src[i]));
            }
        }
    };

    auto compute = [&](const float* buf) {
        #pragma unroll
        for (int k8 = 0; k8 < 4; k8++) {
            uint4 af[2];
            uint2 bf[4];
            #pragma unroll
            for (int mi = 0; mi < 2; mi++)
                af[mi] = *reinterpret_cast<const uint4*>(
                    buf + ((k8 * 8 + wm * 2 + mi) * 32 + lane) * 4);
            #pragma unroll
            for (int ni = 0; ni < 4; ni++)
                bf[ni] = *reinterpret_cast<const uint2*>(
                    buf + AS_FLOATS + ((k8 * 8 + wn * 4 + ni) * 32 + lane) * 2);
            #pragma unroll
            for (int mi = 0; mi < 2; mi++)
                #pragma unroll
                for (int ni = 0; ni < 4; ni++) {
                    float* c = acc[mi * 4 + ni];
                    asm volatile(
                        "mma.sync.aligned.m16n8k8.row.col.f32.tf32.tf32.f32 "
                        "{%0,%1,%2,%3}, {%4,%5,%6,%7}, {%8,%9}, {%0,%1,%2,%3};"
                        : "+f"(c[0]), "+f"(c[1]), "+f"(c[2]), "+f"(c[3])
                        : "r"(af[mi].x), "r"(af[mi].y), "r"(af[mi].z), "r"(af[mi].w),
                          "r"(bf[ni].x), "r"(bf[ni].y));
                }
        }
    };

    constexpr int NIT = KDIM / TBK;
    load_g(0);
    sts(sm);
    __syncthreads();
    for (int kt = 0; kt < NIT; kt++) {
        const float* cur = sm + (size_t)(kt & 1) * BUF_FLOATS;
        float* nxt = sm + (size_t)((kt + 1) & 1) * BUF_FLOATS;
        if (kt + 1 < NIT) load_g(kt + 1);
        compute(cur);
        if (kt + 1 < NIT) sts(nxt);
        __syncthreads();
    }
}

// fuse = relu(v @ W_enc + b_enc) + cat_emb[cat]
__global__ __launch_bounds__(256) void fuse_tc(
    const float* __restrict__ A, const float* __restrict__ W,
    const float* __restrict__ bias, const float* __restrict__ cat_emb)
{
    extern __shared__ float sm[];
    const int brow = blockIdx.y * TBM, bcol = blockIdx.x * TBN;
    float acc[8][4];
    tf32_mainloop<F_, H_>(A, W, sm, brow, bcol, acc);

    const int tid = threadIdx.x, lane = tid & 31, wid = tid >> 5;
    const int wm = wid >> 1, wn = wid & 1;
    #pragma unroll
    for (int mi = 0; mi < 2; mi++)
        #pragma unroll
        for (int ni = 0; ni < 4; ni++) {
            const float* c = acc[mi * 4 + ni];
            int row0 = brow + wm * 32 + mi * 16 + (lane >> 2);
            int col0 = bcol + wn * 32 + ni * 8 + (lane & 3) * 2;
            #pragma unroll
            for (int q = 0; q < 4; q++) {
                int row = row0 + (q >> 1) * 8;
                int col = col0 + (q & 1);
                int b = row >> 6;
                float val = fmaxf(c[q] + bias[col], 0.0f) + cat_emb[g_cat[b] * H_ + col];
                g_fuse[(size_t)row * H_ + col] = val;
            }
        }
}

// x_gates[s][b][g] = fuse @ Wx + (bx+bh), scattered to [S][B][4H]
__global__ __launch_bounds__(256) void xg_tc(
    const float* __restrict__ W, const float* __restrict__ bx,
    const float* __restrict__ bh)
{
    extern __shared__ float sm[];
    const int brow = blockIdx.y * TBM, bcol = blockIdx.x * TBN;
    float acc[8][4];
    tf32_mainloop<H_, G4_>(g_fuse, W, sm, brow, bcol, acc);

    const int tid = threadIdx.x, lane = tid & 31, wid = tid >> 5;
    const int wm = wid >> 1, wn = wid & 1;
    #pragma unroll
    for (int mi = 0; mi < 2; mi++)
        #pragma unroll
        for (int ni = 0; ni < 4; ni++) {
            const float* c = acc[mi * 4 + ni];
            int row0 = brow + wm * 32 + mi * 16 + (lane >> 2);
            int col0 = bcol + wn * 32 + ni * 8 + (lane & 3) * 2;
            #pragma unroll
            for (int q = 0; q < 4; q++) {
                int row = row0 + (q >> 1) * 8;
                int col = col0 + (q & 1);
                int bb = row >> 6, ss = row & 63;
                g_xg[(size_t)(ss * B_ + bb) * G4_ + col] = c[q] + bx[col] + bh[col];
            }
        }
}

// ---------------- persistent LSTM: all 64 steps in one kernel ----------------
// (unchanged from round 7: warp-private K-slices, 4x8 tiles, ticket barrier)
__global__ __launch_bounds__(256) void lstm_persist(const float* __restrict__ Wh)
{
    extern __shared__ float sm[];
    float* whs = sm;                        // [512][16]   32 KB
    float* as_ = sm + 512 * 16;             // [512][64]   128 KB
    float* gs_ = as_ + 512 * 64;            // [8][64*17]  partial gates per warp
    float* cs_ = gs_ + 8 * 64 * 17;         // [64][4]     cell state

    const int tid   = threadIdx.x;
    const int jbase = blockIdx.x * 4;

    const int w = tid >> 5;
    const int l = tid & 31;
    const int r4 = (l & 15) * 4;
    const int c8 = (l >> 4) * 8;

    const int cm  = tid >> 2;
    const int cjl = tid & 3;

    for (int idx = tid; idx < 512 * 16; idx += 256) {
        int k = idx >> 4, c = idx & 15;
        whs[idx] = Wh[(size_t)k * G4_ + (c >> 2) * H_ + jbase + (c & 3)];
    }
    cs_[tid] = 0.0f;
    __syncthreads();

    for (int s = 0; s < S_; s++) {
        const float* __restrict__ hT_in = g_hT[s & 1];
        float* __restrict__ hT_out      = g_hT[(s + 1) & 1];
        const float* __restrict__ xg_s  = &g_xg[(size_t)s * B_ * G4_];

        float acc[4][8];
        #pragma unroll
        for (int i = 0; i < 4; i++)
            #pragma unroll
            for (int j = 0; j < 8; j++) acc[i][j] = 0.0f;

        if (s > 0) {
            const float4* src = reinterpret_cast<const float4*>(hT_in) + w * 1024;
            float4* dst = reinterpret_cast<float4*>(as_ + w * 64 * 64);
            #pragma unroll
            for (int i = 0; i < 32; i++) {
                int f = l + i * 32;
                dst[f] = __ldcg(&src[f]);
            }
            __syncwarp();

            const float* ap = &as_[(w * 64) * 64 + r4];
            const float* bp = &whs[(w * 64) * 16 + c8];
            #pragma unroll 8
            for (int k = 0; k < 64; k++) {
                float4 a  = *reinterpret_cast<const float4*>(ap); ap += 64;
                float4 b0 = *reinterpret_cast<const float4*>(bp);
                float4 b1 = *reinterpret_cast<const float4*>(bp + 4); bp += 16;
                acc[0][0] = fmaf(a.x, b0.x, acc[0][0]);
                acc[1][0] = fmaf(a.y, b0.x, acc[1][0]);
                acc[2][0] = fmaf(a.z, b0.x, acc[2][0]);
                acc[3][0] = fmaf(a.w, b0.x, acc[3][0]);
                acc[0][1] = fmaf(a.x, b0.y, acc[0][1]);
                acc[1][1] = fmaf(a.y, b0.y, acc[1][1]);
                acc[2][1] = fmaf(a.z, b0.y, acc[2][1]);
                acc[3][1] = fmaf(a.w, b0.y, acc[3][1]);
                acc[0][2] = fmaf(a.x, b0.z, acc[0][2]);
                acc[1][2] = fmaf(a.y, b0.z, acc[1][2]);
                acc[2][2] = fmaf(a.z, b0.z, acc[2][2]);
                acc[3][2] = fmaf(a.w, b0.z, acc[3][2]);
                acc[0][3] = fmaf(a.x, b0.w, acc[0][3]);
                acc[1][3] = fmaf(a.y, b0.w, acc[1][3]);
                acc[2][3] = fmaf(a.z, b0.w, acc[2][3]);
                acc[3][3] = fmaf(a.w, b0.w, acc[3][3]);
                acc[0][4] = fmaf(a.x, b1.x, acc[0][4]);
                acc[1][4] = fmaf(a.y, b1.x, acc[1][4]);
                acc[2][4] = fmaf(a.z, b1.x, acc[2][4]);
                acc[3][4] = fmaf(a.w, b1.x, acc[3][4]);
                acc[0][5] = fmaf(a.x, b1.y, acc[0][5]);
                acc[1][5] = fmaf(a.y, b1.y, acc[1][5]);
                acc[2][5] = fmaf(a.z, b1.y, acc[2][5]);
                acc[3][5] = fmaf(a.w, b1.y, acc[3][5]);
                acc[0][6] = fmaf(a.x, b1.z, acc[0][6]);
                acc[1][6] = fmaf(a.y, b1.z, acc[1][6]);
                acc[2][6] = fmaf(a.z, b1.z, acc[2][6]);
                acc[3][6] = fmaf(a.w, b1.z, acc[3][6]);
                acc[0][7] = fmaf(a.x, b1.w, acc[0][7]);
                acc[1][7] = fmaf(a.y, b1.w, acc[1][7]);
                acc[2][7] = fmaf(a.z, b1.w, acc[2][7]);
                acc[3][7] = fmaf(a.w, b1.w, acc[3][7]);
            }
        }

        {
            float* gq = gs_ + w * (64 * 17);
            #pragma unroll
            for (int i = 0; i < 4; i++) {
                #pragma unroll
                for (int j = 0; j < 8; j++)
                    gq[(r4 + i) * 17 + c8 + j] = acc[i][j];
            }
        }
        __syncthreads();

        {
            const int m = cm, jl = cjl;
            float gv[4];
            #pragma unroll
            for (int g = 0; g < 4; g++) {
                float x = xg_s[(size_t)m * G4_ + g * H_ + jbase + jl];
                int o = m * 17 + g * 4 + jl;
                #pragma unroll
                for (int q = 0; q < 8; q++) x += gs_[q * (64 * 17) + o];
                gv[g] = x;
            }
            float co = cs_[m * 4 + jl];
            float cn = sigmoidf_(gv[1]) * co + sigmoidf_(gv[0]) * tanhf(gv[3]);
            float hn = sigmoidf_(gv[2]) * cn;   // NOTE: no tanh on cell
            cs_[m * 4 + jl] = cn;
            __stcg(&hT_out[(jbase + jl) * B_ + m], hn);
        }

        if (s + 1 < S_) {
            __threadfence();
            __syncthreads();
            if (tid == 0) {
                grid_bar_arrive_wait();
                __threadfence();
            }
            __syncthreads();
        }
    }
}

// ---------------- prototype distances -> per-(b,s) W_dd partial --------------
__global__ __launch_bounds__(128) void proto_kernel(
    const float* __restrict__ v, const float* __restrict__ proto,
    const float* __restrict__ W_dd)
{
    const int r = blockIdx.x;
    const int s = r & 63;
    const int tid = threadIdx.x;
    const float* vrow = &v[(size_t)r * F_];

    float acc[P_];
    #pragma unroll
    for (int p = 0; p < P_; p++) acc[p] = 0.0f;

    for (int f = tid; f < F_; f += 128) {
        float vv = vrow[f];
        #pragma unroll
        for (int p = 0; p < P_; p++) {
            float d = vv - proto[p * F_ + f];
            acc[p] = fmaf(d, d, acc[p]);
        }
    }
    #pragma unroll
    for (int p = 0; p < P_; p++) {
        float x = acc[p];
        #pragma unroll
        for (int o = 16; o > 0; o >>= 1) x += __shfl_down_sync(0xffffffffu, x, o);
        acc[p] = x;
    }
    __shared__ float wsum[4][P_];
    __shared__ float psum[P_];
    int wid = tid >> 5, lane = tid & 31;
    if (lane == 0)
        for (int p = 0; p < P_; p++) wsum[wid][p] = acc[p];
    __syncthreads();
    if (tid < P_) {
        float d = wsum[0][tid] + wsum[1][tid] + wsum[2][tid] + wsum[3][tid];
        float df = logf((d + 1.0f) / (d + 1e-8f));
        psum[tid] = df * W_dd[s * P_ + tid];
    }
    __syncthreads();
    if (tid == 0) {
        float t = 0.0f;
        for (int p = 0; p < P_; p++) t += psum[p];
        g_ddp[r] = t;
    }
}

// ---------------- final combine per batch ------------------------------------
__global__ __launch_bounds__(256) void final_kernel(
    const float* __restrict__ v, const float* __restrict__ W_dec,
    const float* __restrict__ b_dec, const float* __restrict__ W_gate,
    const float* __restrict__ b_gate, const float* __restrict__ b_dd,
    float* __restrict__ out)
{
    const int b = blockIdx.x;
    const int tid = threadIdx.x;

    float hd = 0.0f;
    for (int k = tid; k < H_; k += 256)
        hd += g_hT[0][k * B_ + b] * W_dec[k];

    float gs = 0.0f;
    const float* vb = &v[(size_t)b * S_ * F_];
    for (int idx = tid; idx < S_ * F_; idx += 256)
        gs += vb[idx] * W_gate[idx & (F_ - 1)];

    float ds = 0.0f;
    for (int s = tid; s < S_; s += 256)
        ds += g_ddp[b * S_ + s];

    __shared__ float red[3][256];
    red[0][tid] = hd; red[1][tid] = gs; red[2][tid] = ds;
    __syncthreads();
    for (int o = 128; o > 0; o >>= 1) {
        if (tid < o) {
            red[0][tid] += red[0][tid + o];
            red[1][tid] += red[1][tid + o];
            red[2][tid] += red[2][tid + o];
        }
        __syncthreads();
    }
    if (tid == 0) {
        float gt = sigmoidf_(red[1][0] * (1.0f / S_) + b_gate[0]);
        float op = sigmoidf_(red[0][0] + b_dec[0]);
        float dp = sigmoidf_(red[2][0] + b_dd[0]);
        out[b] = op * gt + dp * (1.0f - gt);
    }
}

// ---------------- launch ------------------------------------------------------
extern "C" void kernel_launch(void* const* d_in, const int* in_sizes, int n_in,
                              void* d_out, int out_size)
{
    const float* v       = (const float*)d_in[0];
    const int*   cat     = (const int*)d_in[1];
    const float* W_enc   = (const float*)d_in[2];
    const float* b_enc   = (const float*)d_in[3];
    const float* Wx      = (const float*)d_in[4];
    const float* bx      = (const float*)d_in[5];
    const float* Wh      = (const float*)d_in[6];
    const float* bh      = (const float*)d_in[7];
    const float* cat_emb = (const float*)d_in[8];
    const float* W_dec   = (const float*)d_in[9];
    const float* b_dec   = (const float*)d_in[10];
    const float* proto   = (const float*)d_in[11];
    const float* W_dd    = (const float*)d_in[12];
    const float* b_dd    = (const float*)d_in[13];
    const float* W_gate  = (const float*)d_in[14];
    const float* b_gate  = (const float*)d_in[15];
    float* out = (float*)d_out;

    const int gemm_smem = 2 * BUF_FLOATS * 4;   // 48 KB
    const int lstm_smem = (512 * 16 + 512 * 64 + 8 * 64 * 17 + 64 * 4) * 4;
    cudaFuncSetAttribute(fuse_tc, cudaFuncAttributeMaxDynamicSharedMemorySize, gemm_smem);
    cudaFuncSetAttribute(xg_tc, cudaFuncAttributeMaxDynamicSharedMemorySize, gemm_smem);
    cudaFuncSetAttribute(lstm_persist, cudaFuncAttributeMaxDynamicSharedMemorySize,
                         lstm_smem);

    cat_normalize<<<1, 32>>>(cat);
    fuse_tc<<<dim3(H_ / TBN, R_ / TBM), 256, gemm_smem>>>(v, W_enc, b_enc, cat_emb);
    xg_tc<<<dim3(G4_ / TBN, R_ / TBM), 256, gemm_smem>>>(Wx, bx, bh);
    lstm_persist<<<128, 256, lstm_smem>>>(Wh);
    proto_kernel<<<R_, 128>>>(v, proto, W_dd);
    final_kernel<<<B_, 256>>>(v, W_dec, b_dec, W_gate, b_gate, b_dd, out);
}

// round 10
// speedup vs baseline: 2.1479x; 1.2852x over previous
#include <cuda_runtime.h>
#include <math.h>
#include <stdint.h>

#define B_  64
#define S_  64
#define F_  2048
#define H_  512
#define G4_ 2048
#define P_  20
#define R_  4096   // B*S

// ---------------- scratch (static device globals; no allocs) ----------------
__device__ float g_fuse[R_ * H_];        // [B*S, H]   8 MB
__device__ float g_xg[S_ * B_ * G4_];    // [S][B][4H] 32 MB
__device__ float g_hT[2][H_ * B_];       // hidden state, TRANSPOSED [k][batch]
__device__ float g_ddp[B_ * S_];         // per-(b,s) prototype partial
__device__ int   g_cat[B_];              // normalized category
__device__ unsigned g_bar_count = 0u;    // monotonic ticket counter (never reset)

__device__ __forceinline__ float sigmoidf_(float x) { return 1.0f / (1.0f + expf(-x)); }

__device__ __forceinline__ void grid_bar_arrive_wait() {
    unsigned ticket = atomicAdd(&g_bar_count, 1u);
    unsigned target = (ticket & ~127u) + 128u;
    while (*((volatile unsigned*)&g_bar_count) < target) __nanosleep(32);
}

// ---------------- category dtype normalization (int64 vs int32) -------------
__global__ void cat_normalize(const int* __restrict__ w) {
    if (threadIdx.x == 0 && blockIdx.x == 0) {
        bool oddzero = true, evenok = true;
        for (int i = 0; i < 32; i++) {
            int lo = w[2 * i], hi = w[2 * i + 1];
            if (hi != 0) oddzero = false;
            if (lo < 0 || lo > 2) evenok = false;
        }
        if (oddzero && evenok) {
            const long long* c = (const long long*)w;
            for (int b = 0; b < B_; b++) g_cat[b] = (int)c[b];
        } else {
            for (int b = 0; b < B_; b++) g_cat[b] = w[b];
        }
    }
}

// =================== tf32 tensor-core GEMM (both big GEMMs) ==================
// Block tile 128(M) x 64(N) x 32(K), 256 threads = 8 warps in 4x2 grid,
// warp tile 32x32 (2 m-tiles x 4 n-tiles of m16n8k8). Fragment-packed smem
// with XOR bank swizzle: A frag-lane ^= k8, B frag-lane ^= 2*ntile.
#define TBM 128
#define TBN 64
#define TBK 32
#define AS_FLOATS 4096          // 4 k8 * 8 mtile * 32 * 4
#define BUF_FLOATS 6144         // + 4 k8 * 8 ntile * 32 * 2

__device__ __forceinline__ unsigned f2tf32(float x) {
    unsigned u;
    asm("cvt.rna.tf32.f32 %0, %1;" : "=r"(u) : "f"(x));
    return u;
}

template<int KDIM, int NDIM>
__device__ __forceinline__ void tf32_mainloop(
    const float* __restrict__ A, const float* __restrict__ W,
    float* sm, int brow, int bcol, float (&acc)[8][4])
{
    const int tid  = threadIdx.x;
    const int lane = tid & 31;
    const int wid  = tid >> 5;
    const int wm   = wid >> 1;   // 0..3
    const int wn   = wid & 1;    // 0..1

    #pragma unroll
    for (int i = 0; i < 8; i++)
        #pragma unroll
        for (int j = 0; j < 4; j++) acc[i][j] = 0.0f;

    float4 a_ld[4], b_ld[2];

    auto load_g = [&](int kt) {
        #pragma unroll
        for (int j = 0; j < 4; j++) {
            int r = (tid >> 3) + j * 32;
            a_ld[j] = *reinterpret_cast<const float4*>(
                &A[(size_t)(brow + r) * KDIM + kt * TBK + (tid & 7) * 4]);
        }
        #pragma unroll
        for (int j = 0; j < 2; j++) {
            int f = tid + j * 256;
            int kr = f >> 4, c4 = (f & 15) * 4;
            b_ld[j] = *reinterpret_cast<const float4*>(
                &W[(size_t)(kt * TBK + kr) * NDIM + bcol + c4]);
        }
    };

    auto sts = [&](float* buf) {
        // A fragments (swizzle: frag-lane ^= k8)
        #pragma unroll
        for (int j = 0; j < 4; j++) {
            int r = (tid >> 3) + j * 32;
            int c = (tid & 7) * 4;
            int mtile = r >> 4, rr = r & 15;
            int k8 = c >> 3;
            int sbase = (rr >> 3) + 2 * ((c >> 2) & 1);
            int lbase = (rr & 7) * 4;
            float* dst = buf + ((k8 * 8 + mtile) * 32) * 4 + sbase;
            const float* src = (const float*)&a_ld[j];
            #pragma unroll
            for (int i = 0; i < 4; i++)
                dst[(lbase + (i ^ k8)) * 4] = __uint_as_float(f2tf32(src[i]));
        }
        // B fragments (swizzle: frag-lane ^= 2*ntile)
        #pragma unroll
        for (int j = 0; j < 2; j++) {
            int f = tid + j * 256;
            int kr = f >> 4, c4 = (f & 15) * 4;
            int k8 = kr >> 3, kk = kr & 7;
            int slot = kk >> 2, lrow = kk & 3;
            const float* src = (const float*)&b_ld[j];
            #pragma unroll
            for (int i = 0; i < 4; i++) {
                int c = c4 + i;
                int ntile = c >> 3, cc = c & 7;
                int fsw = (cc * 4 + lrow) ^ (2 * ntile);
                buf[AS_FLOATS + ((k8 * 8 + ntile) * 32 + fsw) * 2 + slot] =
                    __uint_as_float(f2tf32(src[i]));
            }
        }
    };

    auto compute = [&](const float* buf) {
        #pragma unroll
        for (int k8 = 0; k8 < 4; k8++) {
            uint4 af[2];
            uint2 bf[4];
            #pragma unroll
            for (int mi = 0; mi < 2; mi++)
                af[mi] = *reinterpret_cast<const uint4*>(
                    buf + ((k8 * 8 + wm * 2 + mi) * 32 + (lane ^ k8)) * 4);
            #pragma unroll
            for (int ni = 0; ni < 4; ni++) {
                int nt = wn * 4 + ni;
                bf[ni] = *reinterpret_cast<const uint2*>(
                    buf + AS_FLOATS + ((k8 * 8 + nt) * 32 + (lane ^ (2 * nt))) * 2);
            }
            #pragma unroll
            for (int mi = 0; mi < 2; mi++)
                #pragma unroll
                for (int ni = 0; ni < 4; ni++) {
                    float* c = acc[mi * 4 + ni];
                    asm volatile(
                        "mma.sync.aligned.m16n8k8.row.col.f32.tf32.tf32.f32 "
                        "{%0,%1,%2,%3}, {%4,%5,%6,%7}, {%8,%9}, {%0,%1,%2,%3};"
                        : "+f"(c[0]), "+f"(c[1]), "+f"(c[2]), "+f"(c[3])
                        : "r"(af[mi].x), "r"(af[mi].y), "r"(af[mi].z), "r"(af[mi].w),
                          "r"(bf[ni].x), "r"(bf[ni].y));
                }
        }
    };

    constexpr int NIT = KDIM / TBK;
    load_g(0);
    sts(sm);
    __syncthreads();
    for (int kt = 0; kt < NIT; kt++) {
        const float* cur = sm + (size_t)(kt & 1) * BUF_FLOATS;
        float* nxt = sm + (size_t)((kt + 1) & 1) * BUF_FLOATS;
        if (kt + 1 < NIT) load_g(kt + 1);
        compute(cur);
        if (kt + 1 < NIT) sts(nxt);
        __syncthreads();
    }
}

// fuse = relu(v @ W_enc + b_enc) + cat_emb[cat]
__global__ __launch_bounds__(256) void fuse_tc(
    const float* __restrict__ A, const float* __restrict__ W,
    const float* __restrict__ bias, const float* __restrict__ cat_emb)
{
    extern __shared__ float sm[];
    const int brow = blockIdx.y * TBM, bcol = blockIdx.x * TBN;
    float acc[8][4];
    tf32_mainloop<F_, H_>(A, W, sm, brow, bcol, acc);

    const int tid = threadIdx.x, lane = tid & 31, wid = tid >> 5;
    const int wm = wid >> 1, wn = wid & 1;
    #pragma unroll
    for (int mi = 0; mi < 2; mi++)
        #pragma unroll
        for (int ni = 0; ni < 4; ni++) {
            const float* c = acc[mi * 4 + ni];
            int row0 = brow + wm * 32 + mi * 16 + (lane >> 2);
            int col0 = bcol + wn * 32 + ni * 8 + (lane & 3) * 2;
            #pragma unroll
            for (int q = 0; q < 4; q++) {
                int row = row0 + (q >> 1) * 8;
                int col = col0 + (q & 1);
                int b = row >> 6;
                float val = fmaxf(c[q] + bias[col], 0.0f) + cat_emb[g_cat[b] * H_ + col];
                g_fuse[(size_t)row * H_ + col] = val;
            }
        }
}

// x_gates[s][b][g] = fuse @ Wx + (bx+bh), scattered to [S][B][4H]
__global__ __launch_bounds__(256) void xg_tc(
    const float* __restrict__ W, const float* __restrict__ bx,
    const float* __restrict__ bh)
{
    extern __shared__ float sm[];
    const int brow = blockIdx.y * TBM, bcol = blockIdx.x * TBN;
    float acc[8][4];
    tf32_mainloop<H_, G4_>(g_fuse, W, sm, brow, bcol, acc);

    const int tid = threadIdx.x, lane = tid & 31, wid = tid >> 5;
    const int wm = wid >> 1, wn = wid & 1;
    #pragma unroll
    for (int mi = 0; mi < 2; mi++)
        #pragma unroll
        for (int ni = 0; ni < 4; ni++) {
            const float* c = acc[mi * 4 + ni];
            int row0 = brow + wm * 32 + mi * 16 + (lane >> 2);
            int col0 = bcol + wn * 32 + ni * 8 + (lane & 3) * 2;
            #pragma unroll
            for (int q = 0; q < 4; q++) {
                int row = row0 + (q >> 1) * 8;
                int col = col0 + (q & 1);
                int bb = row >> 6, ss = row & 63;
                g_xg[(size_t)(ss * B_ + bb) * G4_ + col] = c[q] + bx[col] + bh[col];
            }
        }
}

// ---------------- persistent LSTM: all 64 steps in one kernel ----------------
// (unchanged: warp-private K-slices, 4x8 tiles, ticket barrier)
__global__ __launch_bounds__(256) void lstm_persist(const float* __restrict__ Wh)
{
    extern __shared__ float sm[];
    float* whs = sm;                        // [512][16]   32 KB
    float* as_ = sm + 512 * 16;             // [512][64]   128 KB
    float* gs_ = as_ + 512 * 64;            // [8][64*17]  partial gates per warp
    float* cs_ = gs_ + 8 * 64 * 17;         // [64][4]     cell state

    const int tid   = threadIdx.x;
    const int jbase = blockIdx.x * 4;

    const int w = tid >> 5;
    const int l = tid & 31;
    const int r4 = (l & 15) * 4;
    const int c8 = (l >> 4) * 8;

    const int cm  = tid >> 2;
    const int cjl = tid & 3;

    for (int idx = tid; idx < 512 * 16; idx += 256) {
        int k = idx >> 4, c = idx & 15;
        whs[idx] = Wh[(size_t)k * G4_ + (c >> 2) * H_ + jbase + (c & 3)];
    }
    cs_[tid] = 0.0f;
    __syncthreads();

    for (int s = 0; s < S_; s++) {
        const float* __restrict__ hT_in = g_hT[s & 1];
        float* __restrict__ hT_out      = g_hT[(s + 1) & 1];
        const float* __restrict__ xg_s  = &g_xg[(size_t)s * B_ * G4_];

        float acc[4][8];
        #pragma unroll
        for (int i = 0; i < 4; i++)
            #pragma unroll
            for (int j = 0; j < 8; j++) acc[i][j] = 0.0f;

        if (s > 0) {
            const float4* src = reinterpret_cast<const float4*>(hT_in) + w * 1024;
            float4* dst = reinterpret_cast<float4*>(as_ + w * 64 * 64);
            #pragma unroll
            for (int i = 0; i < 32; i++) {
                int f = l + i * 32;
                dst[f] = __ldcg(&src[f]);
            }
            __syncwarp();

            const float* ap = &as_[(w * 64) * 64 + r4];
            const float* bp = &whs[(w * 64) * 16 + c8];
            #pragma unroll 8
            for (int k = 0; k < 64; k++) {
                float4 a  = *reinterpret_cast<const float4*>(ap); ap += 64;
                float4 b0 = *reinterpret_cast<const float4*>(bp);
                float4 b1 = *reinterpret_cast<const float4*>(bp + 4); bp += 16;
                acc[0][0] = fmaf(a.x, b0.x, acc[0][0]);
                acc[1][0] = fmaf(a.y, b0.x, acc[1][0]);
                acc[2][0] = fmaf(a.z, b0.x, acc[2][0]);
                acc[3][0] = fmaf(a.w, b0.x, acc[3][0]);
                acc[0][1] = fmaf(a.x, b0.y, acc[0][1]);
                acc[1][1] = fmaf(a.y, b0.y, acc[1][1]);
                acc[2][1] = fmaf(a.z, b0.y, acc[2][1]);
                acc[3][1] = fmaf(a.w, b0.y, acc[3][1]);
                acc[0][2] = fmaf(a.x, b0.z, acc[0][2]);
                acc[1][2] = fmaf(a.y, b0.z, acc[1][2]);
                acc[2][2] = fmaf(a.z, b0.z, acc[2][2]);
                acc[3][2] = fmaf(a.w, b0.z, acc[3][2]);
                acc[0][3] = fmaf(a.x, b0.w, acc[0][3]);
                acc[1][3] = fmaf(a.y, b0.w, acc[1][3]);
                acc[2][3] = fmaf(a.z, b0.w, acc[2][3]);
                acc[3][3] = fmaf(a.w, b0.w, acc[3][3]);
                acc[0][4] = fmaf(a.x, b1.x, acc[0][4]);
                acc[1][4] = fmaf(a.y, b1.x, acc[1][4]);
                acc[2][4] = fmaf(a.z, b1.x, acc[2][4]);
                acc[3][4] = fmaf(a.w, b1.x, acc[3][4]);
                acc[0][5] = fmaf(a.x, b1.y, acc[0][5]);
                acc[1][5] = fmaf(a.y, b1.y, acc[1][5]);
                acc[2][5] = fmaf(a.z, b1.y, acc[2][5]);
                acc[3][5] = fmaf(a.w, b1.y, acc[3][5]);
                acc[0][6] = fmaf(a.x, b1.z, acc[0][6]);
                acc[1][6] = fmaf(a.y, b1.z, acc[1][6]);
                acc[2][6] = fmaf(a.z, b1.z, acc[2][6]);
                acc[3][6] = fmaf(a.w, b1.z, acc[3][6]);
                acc[0][7] = fmaf(a.x, b1.w, acc[0][7]);
                acc[1][7] = fmaf(a.y, b1.w, acc[1][7]);
                acc[2][7] = fmaf(a.z, b1.w, acc[2][7]);
                acc[3][7] = fmaf(a.w, b1.w, acc[3][7]);
            }
        }

        {
            float* gq = gs_ + w * (64 * 17);
            #pragma unroll
            for (int i = 0; i < 4; i++) {
                #pragma unroll
                for (int j = 0; j < 8; j++)
                    gq[(r4 + i) * 17 + c8 + j] = acc[i][j];
            }
        }
        __syncthreads();

        {
            const int m = cm, jl = cjl;
            float gv[4];
            #pragma unroll
            for (int g = 0; g < 4; g++) {
                float x = xg_s[(size_t)m * G4_ + g * H_ + jbase + jl];
                int o = m * 17 + g * 4 + jl;
                #pragma unroll
                for (int q = 0; q < 8; q++) x += gs_[q * (64 * 17) + o];
                gv[g] = x;
            }
            float co = cs_[m * 4 + jl];
            float cn = sigmoidf_(gv[1]) * co + sigmoidf_(gv[0]) * tanhf(gv[3]);
            float hn = sigmoidf_(gv[2]) * cn;   // NOTE: no tanh on cell
            cs_[m * 4 + jl] = cn;
            __stcg(&hT_out[(jbase + jl) * B_ + m], hn);
        }

        if (s + 1 < S_) {
            __threadfence();
            __syncthreads();
            if (tid == 0) {
                grid_bar_arrive_wait();
                __threadfence();
            }
            __syncthreads();
        }
    }
}

// ---------------- prototype distances -> per-(b,s) W_dd partial --------------
__global__ __launch_bounds__(128) void proto_kernel(
    const float* __restrict__ v, const float* __restrict__ proto,
    const float* __restrict__ W_dd)
{
    const int r = blockIdx.x;
    const int s = r & 63;
    const int tid = threadIdx.x;
    const float* vrow = &v[(size_t)r * F_];

    float acc[P_];
    #pragma unroll
    for (int p = 0; p < P_; p++) acc[p] = 0.0f;

    for (int f = tid; f < F_; f += 128) {
        float vv = vrow[f];
        #pragma unroll
        for (int p = 0; p < P_; p++) {
            float d = vv - proto[p * F_ + f];
            acc[p] = fmaf(d, d, acc[p]);
        }
    }
    #pragma unroll
    for (int p = 0; p < P_; p++) {
        float x = acc[p];
        #pragma unroll
        for (int o = 16; o > 0; o >>= 1) x += __shfl_down_sync(0xffffffffu, x, o);
        acc[p] = x;
    }
    __shared__ float wsum[4][P_];
    __shared__ float psum[P_];
    int wid = tid >> 5, lane = tid & 31;
    if (lane == 0)
        for (int p = 0; p < P_; p++) wsum[wid][p] = acc[p];
    __syncthreads();
    if (tid < P_) {
        float d = wsum[0][tid] + wsum[1][tid] + wsum[2][tid] + wsum[3][tid];
        float df = logf((d + 1.0f) / (d + 1e-8f));
        psum[tid] = df * W_dd[s * P_ + tid];
    }
    __syncthreads();
    if (tid == 0) {
        float t = 0.0f;
        for (int p = 0; p < P_; p++) t += psum[p];
        g_ddp[r] = t;
    }
}

// ---------------- final combine per batch ------------------------------------
__global__ __launch_bounds__(256) void final_kernel(
    const float* __restrict__ v, const float* __restrict__ W_dec,
    const float* __restrict__ b_dec, const float* __restrict__ W_gate,
    const float* __restrict__ b_gate, const float* __restrict__ b_dd,
    float* __restrict__ out)
{
    const int b = blockIdx.x;
    const int tid = threadIdx.x;

    float hd = 0.0f;
    for (int k = tid; k < H_; k += 256)
        hd += g_hT[0][k * B_ + b] * W_dec[k];

    float gs = 0.0f;
    const float* vb = &v[(size_t)b * S_ * F_];
    for (int idx = tid; idx < S_ * F_; idx += 256)
        gs += vb[idx] * W_gate[idx & (F_ - 1)];

    float ds = 0.0f;
    for (int s = tid; s < S_; s += 256)
        ds += g_ddp[b * S_ + s];

    __shared__ float red[3][256];
    red[0][tid] = hd; red[1][tid] = gs; red[2][tid] = ds;
    __syncthreads();
    for (int o = 128; o > 0; o >>= 1) {
        if (tid < o) {
            red[0][tid] += red[0][tid + o];
            red[1][tid] += red[1][tid + o];
            red[2][tid] += red[2][tid + o];
        }
        __syncthreads();
    }
    if (tid == 0) {
        float gt = sigmoidf_(red[1][0] * (1.0f / S_) + b_gate[0]);
        float op = sigmoidf_(red[0][0] + b_dec[0]);
        float dp = sigmoidf_(red[2][0] + b_dd[0]);
        out[b] = op * gt + dp * (1.0f - gt);
    }
}

// ---------------- launch ------------------------------------------------------
extern "C" void kernel_launch(void* const* d_in, const int* in_sizes, int n_in,
                              void* d_out, int out_size)
{
    const float* v       = (const float*)d_in[0];
    const int*   cat     = (const int*)d_in[1];
    const float* W_enc   = (const float*)d_in[2];
    const float* b_enc   = (const float*)d_in[3];
    const float* Wx      = (const float*)d_in[4];
    const float* bx      = (const float*)d_in[5];
    const float* Wh      = (const float*)d_in[6];
    const float* bh      = (const float*)d_in[7];
    const float* cat_emb = (const float*)d_in[8];
    const float* W_dec   = (const float*)d_in[9];
    const float* b_dec   = (const float*)d_in[10];
    const float* proto   = (const float*)d_in[11];
    const float* W_dd    = (const float*)d_in[12];
    const float* b_dd    = (const float*)d_in[13];
    const float* W_gate  = (const float*)d_in[14];
    const float* b_gate  = (const float*)d_in[15];
    float* out = (float*)d_out;

    const int gemm_smem = 2 * BUF_FLOATS * 4;   // 48 KB
    const int lstm_smem = (512 * 16 + 512 * 64 + 8 * 64 * 17 + 64 * 4) * 4;
    cudaFuncSetAttribute(fuse_tc, cudaFuncAttributeMaxDynamicSharedMemorySize, gemm_smem);
    cudaFuncSetAttribute(xg_tc, cudaFuncAttributeMaxDynamicSharedMemorySize, gemm_smem);
    cudaFuncSetAttribute(lstm_persist, cudaFuncAttributeMaxDynamicSharedMemorySize,
                         lstm_smem);

    cat_normalize<<<1, 32>>>(cat);
    fuse_tc<<<dim3(H_ / TBN, R_ / TBM), 256, gemm_smem>>>(v, W_enc, b_enc, cat_emb);
    xg_tc<<<dim3(G4_ / TBN, R_ / TBM), 256, gemm_smem>>>(Wx, bx, bh);
    lstm_persist<<<128, 256, lstm_smem>>>(Wh);
    proto_kernel<<<R_, 128>>>(v, proto, W_dd);
    final_kernel<<<B_, 256>>>(v, W_dec, b_dec, W_gate, b_gate, b_dd, out);
}

// round 12
// speedup vs baseline: 2.5082x; 1.1678x over previous
#include <cuda_runtime.h>
#include <math.h>
#include <stdint.h>

#define B_  64
#define S_  64
#define F_  2048
#define H_  512
#define G4_ 2048
#define P_  20
#define R_  4096   // B*S

// ---------------- scratch (static device globals; no allocs) ----------------
__device__ float g_fuse[R_ * H_];        // [B*S, H]   8 MB
__device__ float g_xg[S_ * B_ * G4_];    // [S][B][4H] 32 MB
__device__ float g_hT[2][H_ * B_];       // hidden state, TRANSPOSED [k][batch]
__device__ float g_ddp[B_ * S_];         // per-(b,s) prototype partial
__device__ int   g_cat[B_];              // normalized category
__device__ unsigned g_bar_count = 0u;    // monotonic ticket counter (never reset)

__device__ __forceinline__ float sigmoidf_(float x) { return 1.0f / (1.0f + expf(-x)); }

__device__ __forceinline__ void grid_bar_arrive_wait() {
    unsigned ticket = atomicAdd(&g_bar_count, 1u);
    unsigned target = (ticket & ~127u) + 128u;
    while (*((volatile unsigned*)&g_bar_count) < target) __nanosleep(32);
}

__device__ __forceinline__ unsigned f2tf32(float x) {
    unsigned u;
    asm("cvt.rna.tf32.f32 %0, %1;" : "=r"(u) : "f"(x));
    return u;
}

// ---------------- category dtype normalization (int64 vs int32) -------------
__global__ void cat_normalize(const int* __restrict__ w) {
    if (threadIdx.x == 0 && blockIdx.x == 0) {
        bool oddzero = true, evenok = true;
        for (int i = 0; i < 32; i++) {
            int lo = w[2 * i], hi = w[2 * i + 1];
            if (hi != 0) oddzero = false;
            if (lo < 0 || lo > 2) evenok = false;
        }
        if (oddzero && evenok) {
            const long long* c = (const long long*)w;
            for (int b = 0; b < B_; b++) g_cat[b] = (int)c[b];
        } else {
            for (int b = 0; b < B_; b++) g_cat[b] = w[b];
        }
    }
}

// =================== tf32 tensor-core GEMM (both big GEMMs) ==================
#define TBM 128
#define TBN 64
#define TBK 32
#define AS_FLOATS 4096
#define BUF_FLOATS 6144

template<int KDIM, int NDIM>
__device__ __forceinline__ void tf32_mainloop(
    const float* __restrict__ A, const float* __restrict__ W,
    float* sm, int brow, int bcol, float (&acc)[8][4])
{
    const int tid  = threadIdx.x;
    const int lane = tid & 31;
    const int wid  = tid >> 5;
    const int wm   = wid >> 1;
    const int wn   = wid & 1;

    #pragma unroll
    for (int i = 0; i < 8; i++)
        #pragma unroll
        for (int j = 0; j < 4; j++) acc[i][j] = 0.0f;

    float4 a_ld[4], b_ld[2];

    auto load_g = [&](int kt) {
        #pragma unroll
        for (int j = 0; j < 4; j++) {
            int r = (tid >> 3) + j * 32;
            a_ld[j] = *reinterpret_cast<const float4*>(
                &A[(size_t)(brow + r) * KDIM + kt * TBK + (tid & 7) * 4]);
        }
        #pragma unroll
        for (int j = 0; j < 2; j++) {
            int f = tid + j * 256;
            int kr = f >> 4, c4 = (f & 15) * 4;
            b_ld[j] = *reinterpret_cast<const float4*>(
                &W[(size_t)(kt * TBK + kr) * NDIM + bcol + c4]);
        }
    };

    auto sts = [&](float* buf) {
        #pragma unroll
        for (int j = 0; j < 4; j++) {
            int r = (tid >> 3) + j * 32;
            int c = (tid & 7) * 4;
            int mtile = r >> 4, rr = r & 15;
            int k8 = c >> 3;
            int sbase = (rr >> 3) + 2 * ((c >> 2) & 1);
            int lbase = (rr & 7) * 4;
            float* dst = buf + ((k8 * 8 + mtile) * 32) * 4 + sbase;
            const float* src = (const float*)&a_ld[j];
            #pragma unroll
            for (int i = 0; i < 4; i++)
                dst[(lbase + (i ^ k8)) * 4] = __uint_as_float(f2tf32(src[i]));
        }
        #pragma unroll
        for (int j = 0; j < 2; j++) {
            int f = tid + j * 256;
            int kr = f >> 4, c4 = (f & 15) * 4;
            int k8 = kr >> 3, kk = kr & 7;
            int slot = kk >> 2, lrow = kk & 3;
            const float* src = (const float*)&b_ld[j];
            #pragma unroll
            for (int i = 0; i < 4; i++) {
                int c = c4 + i;
                int ntile = c >> 3, cc = c & 7;
                int fsw = (cc * 4 + lrow) ^ (2 * ntile);
                buf[AS_FLOATS + ((k8 * 8 + ntile) * 32 + fsw) * 2 + slot] =
                    __uint_as_float(f2tf32(src[i]));
            }
        }
    };

    auto compute = [&](const float* buf) {
        #pragma unroll
        for (int k8 = 0; k8 < 4; k8++) {
            uint4 af[2];
            uint2 bf[4];
            #pragma unroll
            for (int mi = 0; mi < 2; mi++)
                af[mi] = *reinterpret_cast<const uint4*>(
                    buf + ((k8 * 8 + wm * 2 + mi) * 32 + (lane ^ k8)) * 4);
            #pragma unroll
            for (int ni = 0; ni < 4; ni++) {
                int nt = wn * 4 + ni;
                bf[ni] = *reinterpret_cast<const uint2*>(
                    buf + AS_FLOATS + ((k8 * 8 + nt) * 32 + (lane ^ (2 * nt))) * 2);
            }
            #pragma unroll
            for (int mi = 0; mi < 2; mi++)
                #pragma unroll
                for (int ni = 0; ni < 4; ni++) {
                    float* c = acc[mi * 4 + ni];
                    asm volatile(
                        "mma.sync.aligned.m16n8k8.row.col.f32.tf32.tf32.f32 "
                        "{%0,%1,%2,%3}, {%4,%5,%6,%7}, {%8,%9}, {%0,%1,%2,%3};"
                        : "+f"(c[0]), "+f"(c[1]), "+f"(c[2]), "+f"(c[3])
                        : "r"(af[mi].x), "r"(af[mi].y), "r"(af[mi].z), "r"(af[mi].w),
                          "r"(bf[ni].x), "r"(bf[ni].y));
                }
        }
    };

    constexpr int NIT = KDIM / TBK;
    load_g(0);
    sts(sm);
    __syncthreads();
    for (int kt = 0; kt < NIT; kt++) {
        const float* cur = sm + (size_t)(kt & 1) * BUF_FLOATS;
        float* nxt = sm + (size_t)((kt + 1) & 1) * BUF_FLOATS;
        if (kt + 1 < NIT) load_g(kt + 1);
        compute(cur);
        if (kt + 1 < NIT) sts(nxt);
        __syncthreads();
    }
}

// fuse = relu(v @ W_enc + b_enc) + cat_emb[cat]
__global__ __launch_bounds__(256) void fuse_tc(
    const float* __restrict__ A, const float* __restrict__ W,
    const float* __restrict__ bias, const float* __restrict__ cat_emb)
{
    extern __shared__ float sm[];
    const int brow = blockIdx.y * TBM, bcol = blockIdx.x * TBN;
    float acc[8][4];
    tf32_mainloop<F_, H_>(A, W, sm, brow, bcol, acc);

    const int tid = threadIdx.x, lane = tid & 31, wid = tid >> 5;
    const int wm = wid >> 1, wn = wid & 1;
    #pragma unroll
    for (int mi = 0; mi < 2; mi++)
        #pragma unroll
        for (int ni = 0; ni < 4; ni++) {
            const float* c = acc[mi * 4 + ni];
            int row0 = brow + wm * 32 + mi * 16 + (lane >> 2);
            int col0 = bcol + wn * 32 + ni * 8 + (lane & 3) * 2;
            #pragma unroll
            for (int q = 0; q < 4; q++) {
                int row = row0 + (q >> 1) * 8;
                int col = col0 + (q & 1);
                int b = row >> 6;
                float val = fmaxf(c[q] + bias[col], 0.0f) + cat_emb[g_cat[b] * H_ + col];
                g_fuse[(size_t)row * H_ + col] = val;
            }
        }
}

// x_gates[s][b][g] = fuse @ Wx + (bx+bh), scattered to [S][B][4H]
__global__ __launch_bounds__(256) void xg_tc(
    const float* __restrict__ W, const float* __restrict__ bx,
    const float* __restrict__ bh)
{
    extern __shared__ float sm[];
    const int brow = blockIdx.y * TBM, bcol = blockIdx.x * TBN;
    float acc[8][4];
    tf32_mainloop<H_, G4_>(g_fuse, W, sm, brow, bcol, acc);

    const int tid = threadIdx.x, lane = tid & 31, wid = tid >> 5;
    const int wm = wid >> 1, wn = wid & 1;
    #pragma unroll
    for (int mi = 0; mi < 2; mi++)
        #pragma unroll
        for (int ni = 0; ni < 4; ni++) {
            const float* c = acc[mi * 4 + ni];
            int row0 = brow + wm * 32 + mi * 16 + (lane >> 2);
            int col0 = bcol + wn * 32 + ni * 8 + (lane & 3) * 2;
            #pragma unroll
            for (int q = 0; q < 4; q++) {
                int row = row0 + (q >> 1) * 8;
                int col = col0 + (q & 1);
                int bb = row >> 6, ss = row & 63;
                g_xg[(size_t)(ss * B_ + bb) * G4_ + col] = c[q] + bx[col] + bh[col];
            }
        }
}

// ---------------- persistent LSTM: tensor-core recurrent GEMM ----------------
// 128 blocks x 256 threads. Block owns h cols [4b,4b+4) => 16 gate cols.
// 8 warps = 8 K-groups of 64 k; warp-private h slices (no intra-step block
// barriers for the GEMM). Per step, warp w:
//   - loads its 64k x 64m h slice from g_hT (coalesced), converts to tf32,
//     stores to as_[k][m ^ ((k&3)*8)] (swizzled; conflict-free both ways)
//   - computes 4 mtile x 2 ntile m16n8k8 tf32 MMAs over its 8 k8-groups
//     (A frags gathered from as_, B frags LDS.64 from prepacked whsf)
// Partial accs exchanged through gs_, fused cell update, ticket grid barrier.
__global__ __launch_bounds__(256) void lstm_persist(const float* __restrict__ Wh)
{
    extern __shared__ float sm[];
    float* whsf = sm;                  // [64 k8][2 nt][32 lane][2 word]  32 KB (tf32)
    float* as_  = sm + 8192;           // [512 k][64 m] swizzled          128 KB (tf32)
    float* gs_  = as_ + 32768;         // [8][64*17] partial gates        34 KB
    float* cs_  = gs_ + 8 * 64 * 17;   // [64][4] cell state              1 KB

    const int tid   = threadIdx.x;
    const int jbase = blockIdx.x * 4;
    const int w = tid >> 5;
    const int l = tid & 31;

    const int cm  = tid >> 2;          // cell-update (m, jl)
    const int cjl = tid & 3;

    // ---- prepack Wh fragments (once): value b[kk][c] for (k8, ntile) tile ----
    for (int idx = tid; idx < 8192; idx += 256) {
        int word = idx & 1, ll = (idx >> 1) & 31, nt = (idx >> 6) & 1, k8 = idx >> 7;
        int kk = (ll & 3) + word * 4, n = ll >> 2;
        int k = k8 * 8 + kk, c = nt * 8 + n;
        float v = Wh[(size_t)k * G4_ + (c >> 2) * H_ + jbase + (c & 3)];
        whsf[idx] = __uint_as_float(f2tf32(v));
    }
    cs_[tid] = 0.0f;
    __syncthreads();

    for (int s = 0; s < S_; s++) {
        const float* __restrict__ hT_in = g_hT[s & 1];
        float* __restrict__ hT_out      = g_hT[(s + 1) & 1];
        const float* __restrict__ xg_s  = &g_xg[(size_t)s * B_ * G4_];

        float acc[4][2][4];
        #pragma unroll
        for (int mt = 0; mt < 4; mt++)
            #pragma unroll
            for (int nt = 0; nt < 2; nt++)
                #pragma unroll
                for (int q = 0; q < 4; q++) acc[mt][nt][q] = 0.0f;

        if (s > 0) {
            // ---- stage this warp's h slice (tf32, swizzled) ----
            const float4* src = reinterpret_cast<const float4*>(hT_in) + w * 1024;
            #pragma unroll
            for (int i = 0; i < 32; i++) {
                int f = l + i * 32;
                float4 v = __ldcg(&src[f]);
                int k  = w * 64 + (f >> 4);
                int m0 = (f & 15) * 4;
                float4 t;
                t.x = __uint_as_float(f2tf32(v.x));
                t.y = __uint_as_float(f2tf32(v.y));
                t.z = __uint_as_float(f2tf32(v.z));
                t.w = __uint_as_float(f2tf32(v.w));
                *reinterpret_cast<float4*>(&as_[k * 64 + (m0 ^ ((k & 3) * 8))]) = t;
            }
            __syncwarp();

            // ---- MMA over this warp's 8 k8-groups ----
            const int c0 = l & 3;
            const int sw = c0 * 8;
            const int r0 = l >> 2;
            #pragma unroll
            for (int k8l = 0; k8l < 8; k8l++) {
                int k8 = w * 8 + k8l;
                int k0 = k8 * 8 + c0;
                int k1 = k0 + 4;        // (k1 & 3) == c0, same swizzle
                uint2 bf[2];
                #pragma unroll
                for (int nt = 0; nt < 2; nt++)
                    bf[nt] = *reinterpret_cast<const uint2*>(
                        &whsf[((k8 * 2 + nt) * 32 + l) * 2]);
                #pragma unroll
                for (int mt = 0; mt < 4; mt++) {
                    int r = mt * 16 + r0;
                    unsigned a0 = __float_as_uint(as_[k0 * 64 + (r ^ sw)]);
                    unsigned a1 = __float_as_uint(as_[k0 * 64 + ((r + 8) ^ sw)]);
                    unsigned a2 = __float_as_uint(as_[k1 * 64 + (r ^ sw)]);
                    unsigned a3 = __float_as_uint(as_[k1 * 64 + ((r + 8) ^ sw)]);
                    #pragma unroll
                    for (int nt = 0; nt < 2; nt++) {
                        float* c = acc[mt][nt];
                        asm volatile(
                            "mma.sync.aligned.m16n8k8.row.col.f32.tf32.tf32.f32 "
                            "{%0,%1,%2,%3}, {%4,%5,%6,%7}, {%8,%9}, {%0,%1,%2,%3};"
                            : "+f"(c[0]), "+f"(c[1]), "+f"(c[2]), "+f"(c[3])
                            : "r"(a0), "r"(a1), "r"(a2), "r"(a3),
                              "r"(bf[nt].x), "r"(bf[nt].y));
                    }
                }
            }
        }

        // ---- write partial gates (acc layout: row=+8 on q>>1, col=+1 on q&1) --
        {
            float* gq = gs_ + w * (64 * 17);
            #pragma unroll
            for (int mt = 0; mt < 4; mt++)
                #pragma unroll
                for (int nt = 0; nt < 2; nt++)
                    #pragma unroll
                    for (int q = 0; q < 4; q++) {
                        int row = mt * 16 + (l >> 2) + (q >> 1) * 8;
                        int col = nt * 8 + (l & 3) * 2 + (q & 1);
                        gq[row * 17 + col] = acc[mt][nt][q];
                    }
        }
        __syncthreads();

        // ---- fused cell update (one thread per (m, jl)) ----
        {
            const int m = cm, jl = cjl;
            float gv[4];
            #pragma unroll
            for (int g = 0; g < 4; g++) {
                float x = xg_s[(size_t)m * G4_ + g * H_ + jbase + jl];
                int o = m * 17 + g * 4 + jl;
                #pragma unroll
                for (int q = 0; q < 8; q++) x += gs_[q * (64 * 17) + o];
                gv[g] = x;
            }
            float co = cs_[m * 4 + jl];
            float cn = sigmoidf_(gv[1]) * co + sigmoidf_(gv[0]) * tanhf(gv[3]);
            float hn = sigmoidf_(gv[2]) * cn;   // NOTE: no tanh on cell
            cs_[m * 4 + jl] = cn;
            __stcg(&hT_out[(jbase + jl) * B_ + m], hn);
        }

        // ---- grid barrier between steps ----
        if (s + 1 < S_) {
            __threadfence();
            __syncthreads();
            if (tid == 0) {
                grid_bar_arrive_wait();
                __threadfence();
            }
            __syncthreads();
        }
    }
}

// ---------------- prototype distances -> per-(b,s) W_dd partial --------------
__global__ __launch_bounds__(128) void proto_kernel(
    const float* __restrict__ v, const float* __restrict__ proto,
    const float* __restrict__ W_dd)
{
    const int r = blockIdx.x;
    const int s = r & 63;
    const int tid = threadIdx.x;
    const float* vrow = &v[(size_t)r * F_];

    float acc[P_];
    #pragma unroll
    for (int p = 0; p < P_; p++) acc[p] = 0.0f;

    for (int f = tid; f < F_; f += 128) {
        float vv = vrow[f];
        #pragma unroll
        for (int p = 0; p < P_; p++) {
            float d = vv - proto[p * F_ + f];
            acc[p] = fmaf(d, d, acc[p]);
        }
    }
    #pragma unroll
    for (int p = 0; p < P_; p++) {
        float x = acc[p];
        #pragma unroll
        for (int o = 16; o > 0; o >>= 1) x += __shfl_down_sync(0xffffffffu, x, o);
        acc[p] = x;
    }
    __shared__ float wsum[4][P_];
    __shared__ float psum[P_];
    int wid = tid >> 5, lane = tid & 31;
    if (lane == 0)
        for (int p = 0; p < P_; p++) wsum[wid][p] = acc[p];
    __syncthreads();
    if (tid < P_) {
        float d = wsum[0][tid] + wsum[1][tid] + wsum[2][tid] + wsum[3][tid];
        float df = logf((d + 1.0f) / (d + 1e-8f));
        psum[tid] = df * W_dd[s * P_ + tid];
    }
    __syncthreads();
    if (tid == 0) {
        float t = 0.0f;
        for (int p = 0; p < P_; p++) t += psum[p];
        g_ddp[r] = t;
    }
}

// ---------------- final combine per batch ------------------------------------
__global__ __launch_bounds__(256) void final_kernel(
    const float* __restrict__ v, const float* __restrict__ W_dec,
    const float* __restrict__ b_dec, const float* __restrict__ W_gate,
    const float* __restrict__ b_gate, const float* __restrict__ b_dd,
    float* __restrict__ out)
{
    const int b = blockIdx.x;
    const int tid = threadIdx.x;

    float hd = 0.0f;
    for (int k = tid; k < H_; k += 256)
        hd += g_hT[0][k * B_ + b] * W_dec[k];

    float gs = 0.0f;
    const float* vb = &v[(size_t)b * S_ * F_];
    for (int idx = tid; idx < S_ * F_; idx += 256)
        gs += vb[idx] * W_gate[idx & (F_ - 1)];

    float ds = 0.0f;
    for (int s = tid; s < S_; s += 256)
        ds += g_ddp[b * S_ + s];

    __shared__ float red[3][256];
    red[0][tid] = hd; red[1][tid] = gs; red[2][tid] = ds;
    __syncthreads();
    for (int o = 128; o > 0; o >>= 1) {
        if (tid < o) {
            red[0][tid] += red[0][tid + o];
            red[1][tid] += red[1][tid + o];
            red[2][tid] += red[2][tid + o];
        }
        __syncthreads();
    }
    if (tid == 0) {
        float gt = sigmoidf_(red[1][0] * (1.0f / S_) + b_gate[0]);
        float op = sigmoidf_(red[0][0] + b_dec[0]);
        float dp = sigmoidf_(red[2][0] + b_dd[0]);
        out[b] = op * gt + dp * (1.0f - gt);
    }
}

// ---------------- launch ------------------------------------------------------
extern "C" void kernel_launch(void* const* d_in, const int* in_sizes, int n_in,
                              void* d_out, int out_size)
{
    const float* v       = (const float*)d_in[0];
    const int*   cat     = (const int*)d_in[1];
    const float* W_enc   = (const float*)d_in[2];
    const float* b_enc   = (const float*)d_in[3];
    const float* Wx      = (const float*)d_in[4];
    const float* bx      = (const float*)d_in[5];
    const float* Wh      = (const float*)d_in[6];
    const float* bh      = (const float*)d_in[7];
    const float* cat_emb = (const float*)d_in[8];
    const float* W_dec   = (const float*)d_in[9];
    const float* b_dec   = (const float*)d_in[10];
    const float* proto   = (const float*)d_in[11];
    const float* W_dd    = (const float*)d_in[12];
    const float* b_dd    = (const float*)d_in[13];
    const float* W_gate  = (const float*)d_in[14];
    const float* b_gate  = (const float*)d_in[15];
    float* out = (float*)d_out;

    const int gemm_smem = 2 * BUF_FLOATS * 4;                       // 48 KB
    const int lstm_smem = (8192 + 32768 + 8 * 64 * 17 + 256) * 4;   // ~196 KB
    cudaFuncSetAttribute(fuse_tc, cudaFuncAttributeMaxDynamicSharedMemorySize, gemm_smem);
    cudaFuncSetAttribute(xg_tc, cudaFuncAttributeMaxDynamicSharedMemorySize, gemm_smem);
    cudaFuncSetAttribute(lstm_persist, cudaFuncAttributeMaxDynamicSharedMemorySize,
                         lstm_smem);

    cat_normalize<<<1, 32>>>(cat);
    fuse_tc<<<dim3(H_ / TBN, R_ / TBM), 256, gemm_smem>>>(v, W_enc, b_enc, cat_emb);
    xg_tc<<<dim3(G4_ / TBN, R_ / TBM), 256, gemm_smem>>>(Wx, bx, bh);
    lstm_persist<<<128, 256, lstm_smem>>>(Wh);
    proto_kernel<<<R_, 128>>>(v, proto, W_dd);
    final_kernel<<<B_, 256>>>(v, W_dec, b_dec, W_gate, b_gate, b_dd, out);
}

// round 13
// speedup vs baseline: 2.6854x; 1.0706x over previous
#include <cuda_runtime.h>
#include <math.h>
#include <stdint.h>

#define B_  64
#define S_  64
#define F_  2048
#define H_  512
#define G4_ 2048
#define P_  20
#define R_  4096   // B*S

// ---------------- scratch (static device globals; no allocs) ----------------
__device__ float g_fuse[R_ * H_];        // [B*S, H]   8 MB
__device__ float g_xg[S_ * B_ * G4_];    // [S][B][4H] 32 MB
__device__ float g_hT[2][H_ * B_];       // hidden state, TRANSPOSED [k][batch]
__device__ float g_ddp[B_ * S_];         // per-(b,s) prototype partial
__device__ int   g_cat[B_];              // normalized category
__device__ unsigned g_bar_count = 0u;    // monotonic ticket counter (never reset)

__device__ __forceinline__ float sigmoidf_(float x) { return 1.0f / (1.0f + expf(-x)); }

__device__ __forceinline__ float tanh_fast(float x) {
    float r;
    asm("tanh.approx.f32 %0, %1;" : "=f"(r) : "f"(x));
    return r;
}
__device__ __forceinline__ float sig_fast(float x) {
    return fmaf(tanh_fast(0.5f * x), 0.5f, 0.5f);
}

// Ticket barrier with release-fence + acquire-poll (one membar instead of two).
__device__ __forceinline__ void grid_bar_arrive_wait() {
    __threadfence();   // release h stores
    unsigned ticket = atomicAdd(&g_bar_count, 1u);
    unsigned target = (ticket & ~127u) + 128u;
    for (;;) {
        unsigned cur;
        asm volatile("ld.acquire.gpu.u32 %0, [%1];"
                     : "=r"(cur) : "l"(&g_bar_count) : "memory");
        if (cur >= target) break;
        __nanosleep(20);
    }
}

__device__ __forceinline__ unsigned f2tf32(float x) {
    unsigned u;
    asm("cvt.rna.tf32.f32 %0, %1;" : "=r"(u) : "f"(x));
    return u;
}

// ---------------- category dtype normalization (int64 vs int32) -------------
__global__ void cat_normalize(const int* __restrict__ w) {
    if (threadIdx.x == 0 && blockIdx.x == 0) {
        bool oddzero = true, evenok = true;
        for (int i = 0; i < 32; i++) {
            int lo = w[2 * i], hi = w[2 * i + 1];
            if (hi != 0) oddzero = false;
            if (lo < 0 || lo > 2) evenok = false;
        }
        if (oddzero && evenok) {
            const long long* c = (const long long*)w;
            for (int b = 0; b < B_; b++) g_cat[b] = (int)c[b];
        } else {
            for (int b = 0; b < B_; b++) g_cat[b] = w[b];
        }
    }
}

// =================== tf32 tensor-core GEMM (both big GEMMs) ==================
#define TBM 128
#define TBN 64
#define TBK 32
#define AS_FLOATS 4096
#define BUF_FLOATS 6144

template<int KDIM, int NDIM>
__device__ __forceinline__ void tf32_mainloop(
    const float* __restrict__ A, const float* __restrict__ W,
    float* sm, int brow, int bcol, float (&acc)[8][4])
{
    const int tid  = threadIdx.x;
    const int lane = tid & 31;
    const int wid  = tid >> 5;
    const int wm   = wid >> 1;
    const int wn   = wid & 1;

    #pragma unroll
    for (int i = 0; i < 8; i++)
        #pragma unroll
        for (int j = 0; j < 4; j++) acc[i][j] = 0.0f;

    float4 a_ld[4], b_ld[2];

    auto load_g = [&](int kt) {
        #pragma unroll
        for (int j = 0; j < 4; j++) {
            int r = (tid >> 3) + j * 32;
            a_ld[j] = *reinterpret_cast<const float4*>(
                &A[(size_t)(brow + r) * KDIM + kt * TBK + (tid & 7) * 4]);
        }
        #pragma unroll
        for (int j = 0; j < 2; j++) {
            int f = tid + j * 256;
            int kr = f >> 4, c4 = (f & 15) * 4;
            b_ld[j] = *reinterpret_cast<const float4*>(
                &W[(size_t)(kt * TBK + kr) * NDIM + bcol + c4]);
        }
    };

    auto sts = [&](float* buf) {
        #pragma unroll
        for (int j = 0; j < 4; j++) {
            int r = (tid >> 3) + j * 32;
            int c = (tid & 7) * 4;
            int mtile = r >> 4, rr = r & 15;
            int k8 = c >> 3;
            int sbase = (rr >> 3) + 2 * ((c >> 2) & 1);
            int lbase = (rr & 7) * 4;
            float* dst = buf + ((k8 * 8 + mtile) * 32) * 4 + sbase;
            const float* src = (const float*)&a_ld[j];
            #pragma unroll
            for (int i = 0; i < 4; i++)
                dst[(lbase + (i ^ k8)) * 4] = __uint_as_float(f2tf32(src[i]));
        }
        #pragma unroll
        for (int j = 0; j < 2; j++) {
            int f = tid + j * 256;
            int kr = f >> 4, c4 = (f & 15) * 4;
            int k8 = kr >> 3, kk = kr & 7;
            int slot = kk >> 2, lrow = kk & 3;
            const float* src = (const float*)&b_ld[j];
            #pragma unroll
            for (int i = 0; i < 4; i++) {
                int c = c4 + i;
                int ntile = c >> 3, cc = c & 7;
                int fsw = (cc * 4 + lrow) ^ (2 * ntile);
                buf[AS_FLOATS + ((k8 * 8 + ntile) * 32 + fsw) * 2 + slot] =
                    __uint_as_float(f2tf32(src[i]));
            }
        }
    };

    auto compute = [&](const float* buf) {
        #pragma unroll
        for (int k8 = 0; k8 < 4; k8++) {
            uint4 af[2];
            uint2 bf[4];
            #pragma unroll
            for (int mi = 0; mi < 2; mi++)
                af[mi] = *reinterpret_cast<const uint4*>(
                    buf + ((k8 * 8 + wm * 2 + mi) * 32 + (lane ^ k8)) * 4);
            #pragma unroll
            for (int ni = 0; ni < 4; ni++) {
                int nt = wn * 4 + ni;
                bf[ni] = *reinterpret_cast<const uint2*>(
                    buf + AS_FLOATS + ((k8 * 8 + nt) * 32 + (lane ^ (2 * nt))) * 2);
            }
            #pragma unroll
            for (int mi = 0; mi < 2; mi++)
                #pragma unroll
                for (int ni = 0; ni < 4; ni++) {
                    float* c = acc[mi * 4 + ni];
                    asm volatile(
                        "mma.sync.aligned.m16n8k8.row.col.f32.tf32.tf32.f32 "
                        "{%0,%1,%2,%3}, {%4,%5,%6,%7}, {%8,%9}, {%0,%1,%2,%3};"
                        : "+f"(c[0]), "+f"(c[1]), "+f"(c[2]), "+f"(c[3])
                        : "r"(af[mi].x), "r"(af[mi].y), "r"(af[mi].z), "r"(af[mi].w),
                          "r"(bf[ni].x), "r"(bf[ni].y));
                }
        }
    };

    constexpr int NIT = KDIM / TBK;
    load_g(0);
    sts(sm);
    __syncthreads();
    for (int kt = 0; kt < NIT; kt++) {
        const float* cur = sm + (size_t)(kt & 1) * BUF_FLOATS;
        float* nxt = sm + (size_t)((kt + 1) & 1) * BUF_FLOATS;
        if (kt + 1 < NIT) load_g(kt + 1);
        compute(cur);
        if (kt + 1 < NIT) sts(nxt);
        __syncthreads();
    }
}

// fuse = relu(v @ W_enc + b_enc) + cat_emb[cat]
__global__ __launch_bounds__(256) void fuse_tc(
    const float* __restrict__ A, const float* __restrict__ W,
    const float* __restrict__ bias, const float* __restrict__ cat_emb)
{
    extern __shared__ float sm[];
    const int brow = blockIdx.y * TBM, bcol = blockIdx.x * TBN;
    float acc[8][4];
    tf32_mainloop<F_, H_>(A, W, sm, brow, bcol, acc);

    const int tid = threadIdx.x, lane = tid & 31, wid = tid >> 5;
    const int wm = wid >> 1, wn = wid & 1;
    #pragma unroll
    for (int mi = 0; mi < 2; mi++)
        #pragma unroll
        for (int ni = 0; ni < 4; ni++) {
            const float* c = acc[mi * 4 + ni];
            int row0 = brow + wm * 32 + mi * 16 + (lane >> 2);
            int col0 = bcol + wn * 32 + ni * 8 + (lane & 3) * 2;
            #pragma unroll
            for (int q = 0; q < 4; q++) {
                int row = row0 + (q >> 1) * 8;
                int col = col0 + (q & 1);
                int b = row >> 6;
                float val = fmaxf(c[q] + bias[col], 0.0f) + cat_emb[g_cat[b] * H_ + col];
                g_fuse[(size_t)row * H_ + col] = val;
            }
        }
}

// x_gates[s][b][g] = fuse @ Wx + (bx+bh), scattered to [S][B][4H]
__global__ __launch_bounds__(256) void xg_tc(
    const float* __restrict__ W, const float* __restrict__ bx,
    const float* __restrict__ bh)
{
    extern __shared__ float sm[];
    const int brow = blockIdx.y * TBM, bcol = blockIdx.x * TBN;
    float acc[8][4];
    tf32_mainloop<H_, G4_>(g_fuse, W, sm, brow, bcol, acc);

    const int tid = threadIdx.x, lane = tid & 31, wid = tid >> 5;
    const int wm = wid >> 1, wn = wid & 1;
    #pragma unroll
    for (int mi = 0; mi < 2; mi++)
        #pragma unroll
        for (int ni = 0; ni < 4; ni++) {
            const float* c = acc[mi * 4 + ni];
            int row0 = brow + wm * 32 + mi * 16 + (lane >> 2);
            int col0 = bcol + wn * 32 + ni * 8 + (lane & 3) * 2;
            #pragma unroll
            for (int q = 0; q < 4; q++) {
                int row = row0 + (q >> 1) * 8;
                int col = col0 + (q & 1);
                int bb = row >> 6, ss = row & 63;
                g_xg[(size_t)(ss * B_ + bb) * G4_ + col] = c[q] + bx[col] + bh[col];
            }
        }
}

// ---------------- persistent LSTM: tensor-core recurrent GEMM ----------------
// 128 blocks x 256 threads; structure as round 12, plus:
//  - xg for the cell update prefetched at step start (hidden under stage+MMA)
//  - MUFU tanh.approx activations
//  - acquire-poll grid barrier (one membar per step instead of two)
__global__ __launch_bounds__(256) void lstm_persist(const float* __restrict__ Wh)
{
    extern __shared__ float sm[];
    float* whsf = sm;                  // [64 k8][2 nt][32 lane][2 word]  32 KB (tf32)
    float* as_  = sm + 8192;           // [512 k][64 m] swizzled          128 KB (tf32)
    float* gs_  = as_ + 32768;         // [8][64*17] partial gates        34 KB
    float* cs_  = gs_ + 8 * 64 * 17;   // [64][4] cell state              1 KB

    const int tid   = threadIdx.x;
    const int jbase = blockIdx.x * 4;
    const int w = tid >> 5;
    const int l = tid & 31;

    const int cm  = tid >> 2;          // cell-update (m, jl)
    const int cjl = tid & 3;

    // ---- prepack Wh fragments (once) ----
    for (int idx = tid; idx < 8192; idx += 256) {
        int word = idx & 1, ll = (idx >> 1) & 31, nt = (idx >> 6) & 1, k8 = idx >> 7;
        int kk = (ll & 3) + word * 4, n = ll >> 2;
        int k = k8 * 8 + kk, c = nt * 8 + n;
        float v = Wh[(size_t)k * G4_ + (c >> 2) * H_ + jbase + (c & 3)];
        whsf[idx] = __uint_as_float(f2tf32(v));
    }
    cs_[tid] = 0.0f;
    __syncthreads();

    for (int s = 0; s < S_; s++) {
        const float* __restrict__ hT_in = g_hT[s & 1];
        float* __restrict__ hT_out      = g_hT[(s + 1) & 1];
        const float* __restrict__ xg_s  = &g_xg[(size_t)s * B_ * G4_];

        // ---- prefetch cell-update xg (4 loads, MLP 4; retire under stage/MMA)
        float xgp[4];
        #pragma unroll
        for (int g = 0; g < 4; g++)
            xgp[g] = __ldg(&xg_s[(size_t)cm * G4_ + g * H_ + jbase + cjl]);

        float acc[4][2][4];
        #pragma unroll
        for (int mt = 0; mt < 4; mt++)
            #pragma unroll
            for (int nt = 0; nt < 2; nt++)
                #pragma unroll
                for (int q = 0; q < 4; q++) acc[mt][nt][q] = 0.0f;

        if (s > 0) {
            // ---- stage this warp's h slice (tf32, swizzled) ----
            const float4* src = reinterpret_cast<const float4*>(hT_in) + w * 1024;
            #pragma unroll
            for (int i = 0; i < 32; i++) {
                int f = l + i * 32;
                float4 v = __ldcg(&src[f]);
                int k  = w * 64 + (f >> 4);
                int m0 = (f & 15) * 4;
                float4 t;
                t.x = __uint_as_float(f2tf32(v.x));
                t.y = __uint_as_float(f2tf32(v.y));
                t.z = __uint_as_float(f2tf32(v.z));
                t.w = __uint_as_float(f2tf32(v.w));
                *reinterpret_cast<float4*>(&as_[k * 64 + (m0 ^ ((k & 3) * 8))]) = t;
            }
            __syncwarp();

            // ---- MMA over this warp's 8 k8-groups ----
            const int c0 = l & 3;
            const int sw = c0 * 8;
            const int r0 = l >> 2;
            #pragma unroll
            for (int k8l = 0; k8l < 8; k8l++) {
                int k8 = w * 8 + k8l;
                int k0 = k8 * 8 + c0;
                int k1 = k0 + 4;
                uint2 bf[2];
                #pragma unroll
                for (int nt = 0; nt < 2; nt++)
                    bf[nt] = *reinterpret_cast<const uint2*>(
                        &whsf[((k8 * 2 + nt) * 32 + l) * 2]);
                #pragma unroll
                for (int mt = 0; mt < 4; mt++) {
                    int r = mt * 16 + r0;
                    unsigned a0 = __float_as_uint(as_[k0 * 64 + (r ^ sw)]);
                    unsigned a1 = __float_as_uint(as_[k0 * 64 + ((r + 8) ^ sw)]);
                    unsigned a2 = __float_as_uint(as_[k1 * 64 + (r ^ sw)]);
                    unsigned a3 = __float_as_uint(as_[k1 * 64 + ((r + 8) ^ sw)]);
                    #pragma unroll
                    for (int nt = 0; nt < 2; nt++) {
                        float* c = acc[mt][nt];
                        asm volatile(
                            "mma.sync.aligned.m16n8k8.row.col.f32.tf32.tf32.f32 "
                            "{%0,%1,%2,%3}, {%4,%5,%6,%7}, {%8,%9}, {%0,%1,%2,%3};"
                            : "+f"(c[0]), "+f"(c[1]), "+f"(c[2]), "+f"(c[3])
                            : "r"(a0), "r"(a1), "r"(a2), "r"(a3),
                              "r"(bf[nt].x), "r"(bf[nt].y));
                    }
                }
            }
        }

        // ---- write partial gates ----
        {
            float* gq = gs_ + w * (64 * 17);
            #pragma unroll
            for (int mt = 0; mt < 4; mt++)
                #pragma unroll
                for (int nt = 0; nt < 2; nt++)
                    #pragma unroll
                    for (int q = 0; q < 4; q++) {
                        int row = mt * 16 + (l >> 2) + (q >> 1) * 8;
                        int col = nt * 8 + (l & 3) * 2 + (q & 1);
                        gq[row * 17 + col] = acc[mt][nt][q];
                    }
        }
        __syncthreads();

        // ---- fused cell update (one thread per (m, jl)) ----
        {
            const int m = cm, jl = cjl;
            float gv[4];
            #pragma unroll
            for (int g = 0; g < 4; g++) {
                float x = xgp[g];
                int o = m * 17 + g * 4 + jl;
                #pragma unroll
                for (int q = 0; q < 8; q++) x += gs_[q * (64 * 17) + o];
                gv[g] = x;
            }
            float co = cs_[m * 4 + jl];
            float cn = sig_fast(gv[1]) * co + sig_fast(gv[0]) * tanh_fast(gv[3]);
            float hn = sig_fast(gv[2]) * cn;   // NOTE: no tanh on cell
            cs_[m * 4 + jl] = cn;
            __stcg(&hT_out[(jbase + jl) * B_ + m], hn);
        }

        // ---- grid barrier between steps ----
        if (s + 1 < S_) {
            __syncthreads();
            if (tid == 0) grid_bar_arrive_wait();
            __syncthreads();
        }
    }
}

// ---------------- prototype distances -> per-(b,s) W_dd partial --------------
__global__ __launch_bounds__(128) void proto_kernel(
    const float* __restrict__ v, const float* __restrict__ proto,
    const float* __restrict__ W_dd)
{
    const int r = blockIdx.x;
    const int s = r & 63;
    const int tid = threadIdx.x;
    const float* vrow = &v[(size_t)r * F_];

    float acc[P_];
    #pragma unroll
    for (int p = 0; p < P_; p++) acc[p] = 0.0f;

    for (int f = tid; f < F_; f += 128) {
        float vv = vrow[f];
        #pragma unroll
        for (int p = 0; p < P_; p++) {
            float d = vv - proto[p * F_ + f];
            acc[p] = fmaf(d, d, acc[p]);
        }
    }
    #pragma unroll
    for (int p = 0; p < P_; p++) {
        float x = acc[p];
        #pragma unroll
        for (int o = 16; o > 0; o >>= 1) x += __shfl_down_sync(0xffffffffu, x, o);
        acc[p] = x;
    }
    __shared__ float wsum[4][P_];
    __shared__ float psum[P_];
    int wid = tid >> 5, lane = tid & 31;
    if (lane == 0)
        for (int p = 0; p < P_; p++) wsum[wid][p] = acc[p];
    __syncthreads();
    if (tid < P_) {
        float d = wsum[0][tid] + wsum[1][tid] + wsum[2][tid] + wsum[3][tid];
        float df = logf((d + 1.0f) / (d + 1e-8f));
        psum[tid] = df * W_dd[s * P_ + tid];
    }
    __syncthreads();
    if (tid == 0) {
        float t = 0.0f;
        for (int p = 0; p < P_; p++) t += psum[p];
        g_ddp[r] = t;
    }
}

// ---------------- final combine per batch ------------------------------------
__global__ __launch_bounds__(256) void final_kernel(
    const float* __restrict__ v, const float* __restrict__ W_dec,
    const float* __restrict__ b_dec, const float* __restrict__ W_gate,
    const float* __restrict__ b_gate, const float* __restrict__ b_dd,
    float* __restrict__ out)
{
    const int b = blockIdx.x;
    const int tid = threadIdx.x;

    float hd = 0.0f;
    for (int k = tid; k < H_; k += 256)
        hd += g_hT[0][k * B_ + b] * W_dec[k];

    float gs = 0.0f;
    const float* vb = &v[(size_t)b * S_ * F_];
    for (int idx = tid; idx < S_ * F_; idx += 256)
        gs += vb[idx] * W_gate[idx & (F_ - 1)];

    float ds = 0.0f;
    for (int s = tid; s < S_; s += 256)
        ds += g_ddp[b * S_ + s];

    __shared__ float red[3][256];
    red[0][tid] = hd; red[1][tid] = gs; red[2][tid] = ds;
    __syncthreads();
    for (int o = 128; o > 0; o >>= 1) {
        if (tid < o) {
            red[0][tid] += red[0][tid + o];
            red[1][tid] += red[1][tid + o];
            red[2][tid] += red[2][tid + o];
        }
        __syncthreads();
    }
    if (tid == 0) {
        float gt = sigmoidf_(red[1][0] * (1.0f / S_) + b_gate[0]);
        float op = sigmoidf_(red[0][0] + b_dec[0]);
        float dp = sigmoidf_(red[2][0] + b_dd[0]);
        out[b] = op * gt + dp * (1.0f - gt);
    }
}

// ---------------- launch ------------------------------------------------------
extern "C" void kernel_launch(void* const* d_in, const int* in_sizes, int n_in,
                              void* d_out, int out_size)
{
    const float* v       = (const float*)d_in[0];
    const int*   cat     = (const int*)d_in[1];
    const float* W_enc   = (const float*)d_in[2];
    const float* b_enc   = (const float*)d_in[3];
    const float* Wx      = (const float*)d_in[4];
    const float* bx      = (const float*)d_in[5];
    const float* Wh      = (const float*)d_in[6];
    const float* bh      = (const float*)d_in[7];
    const float* cat_emb = (const float*)d_in[8];
    const float* W_dec   = (const float*)d_in[9];
    const float* b_dec   = (const float*)d_in[10];
    const float* proto   = (const float*)d_in[11];
    const float* W_dd    = (const float*)d_in[12];
    const float* b_dd    = (const float*)d_in[13];
    const float* W_gate  = (const float*)d_in[14];
    const float* b_gate  = (const float*)d_in[15];
    float* out = (float*)d_out;

    const int gemm_smem = 2 * BUF_FLOATS * 4;                       // 48 KB
    const int lstm_smem = (8192 + 32768 + 8 * 64 * 17 + 256) * 4;   // ~196 KB
    cudaFuncSetAttribute(fuse_tc, cudaFuncAttributeMaxDynamicSharedMemorySize, gemm_smem);
    cudaFuncSetAttribute(xg_tc, cudaFuncAttributeMaxDynamicSharedMemorySize, gemm_smem);
    cudaFuncSetAttribute(lstm_persist, cudaFuncAttributeMaxDynamicSharedMemorySize,
                         lstm_smem);

    cat_normalize<<<1, 32>>>(cat);
    fuse_tc<<<dim3(H_ / TBN, R_ / TBM), 256, gemm_smem>>>(v, W_enc, b_enc, cat_emb);
    xg_tc<<<dim3(G4_ / TBN, R_ / TBM), 256, gemm_smem>>>(Wx, bx, bh);
    lstm_persist<<<128, 256, lstm_smem>>>(Wh);
    proto_kernel<<<R_, 128>>>(v, proto, W_dd);
    final_kernel<<<B_, 256>>>(v, W_dec, b_dec, W_gate, b_gate, b_dd, out);
}